// round 12
// baseline (speedup 1.0000x reference)
#include <cuda_runtime.h>
#include <cuda_bf16.h>
#include <math.h>
#include <stdint.h>

// ---------------- problem constants ----------------
#define Bsz 2048
#define Ssz 64
#define Cin 142
#define KIN 160
#define Dm  256
#define NH  8
#define DHd 32
#define FFd 512
#define NL  3
#define Ed  128
#define Kcb 1024
#define Tt  65
#define MTOK (Bsz*Tt)
#define MIN0 (Bsz*Ssz)
#define LN_EPS 1e-5f

#define PL0 ((size_t)MTOK*Dm)
#define PL1 ((size_t)MTOK*FFd)
#define PLQ ((size_t)MTOK*3*Dm)
#define PLX ((size_t)MIN0*KIN)
#define WQKV_SZ (3*Dm*Dm)
#define WO_SZ   (Dm*Dm)
#define W1_SZ   (FFd*Dm)
#define W2_SZ   (Dm*FFd)
#define WLAYER  (WQKV_SZ+WO_SZ+W1_SZ+W2_SZ)

// ---------------- scratch ----------------
__device__ float g_h   [(size_t)Bsz*Tt*Dm];
__device__ float g_ze  [(size_t)Bsz*Ed];
__device__ int   g_idx [Bsz];
__device__ float g_cnorm[Kcb];
__device__ int   g_hist[Kcb];
__device__ float g_losspart[Bsz];

__device__ __nv_bfloat16 g_act0[2*PL0];
__device__ __nv_bfloat16 g_act1[2*PL1];
__device__ __nv_bfloat16 g_qkvb[2*PLQ];
__device__ __nv_bfloat16 g_xb  [2*PLX];
__device__ __nv_bfloat16 g_winb[2*Dm*KIN];
__device__ __nv_bfloat16 g_wqkvb[(size_t)NL*2*WQKV_SZ];
__device__ __nv_bfloat16 g_wob  [(size_t)NL*2*WO_SZ];
__device__ __nv_bfloat16 g_w1b  [(size_t)NL*2*W1_SZ];
__device__ __nv_bfloat16 g_w2b  [(size_t)NL*2*W2_SZ];

// ---------------- low-level helpers ----------------
__device__ __forceinline__ uint32_t smem_to_u32(const void* p) {
    uint32_t a;
    asm("{ .reg .u64 t; cvta.to.shared.u64 t, %1; cvt.u32.u64 %0, t; }" : "=r"(a) : "l"(p));
    return a;
}
__device__ __forceinline__ void cp_async16(uint32_t saddr, const void* gaddr) {
    asm volatile("cp.async.cg.shared.global [%0], [%1], 16;" :: "r"(saddr), "l"(gaddr));
}
__device__ __forceinline__ void ldsm4(uint32_t* r, uint32_t addr) {
    asm volatile("ldmatrix.sync.aligned.m8n8.x4.shared.b16 {%0,%1,%2,%3}, [%4];"
        : "=r"(r[0]), "=r"(r[1]), "=r"(r[2]), "=r"(r[3]) : "r"(addr));
}
__device__ __forceinline__ void mma16816(float* c, const uint32_t* a, const uint32_t* b) {
    asm volatile(
        "mma.sync.aligned.m16n8k16.row.col.f32.bf16.bf16.f32 "
        "{%0,%1,%2,%3}, {%4,%5,%6,%7}, {%8,%9}, {%0,%1,%2,%3};"
        : "+f"(c[0]), "+f"(c[1]), "+f"(c[2]), "+f"(c[3])
        : "r"(a[0]), "r"(a[1]), "r"(a[2]), "r"(a[3]), "r"(b[0]), "r"(b[1]));
}
__device__ __forceinline__ float gelu_exact(float x) {
    return 0.5f * x * (1.0f + erff(x * 0.7071067811865475f));
}
__device__ __forceinline__ void split2(float v, __nv_bfloat16& h, __nv_bfloat16& l) {
    h = __float2bfloat16(v);
    l = __float2bfloat16(v - __bfloat162float(h));
}
__device__ __forceinline__ float bred256(float v, float* sm) {
    int tid = threadIdx.x;
    #pragma unroll
    for (int o = 16; o > 0; o >>= 1) v += __shfl_down_sync(0xffffffffu, v, o);
    if ((tid & 31) == 0) sm[tid >> 5] = v;
    __syncthreads();
    if (tid == 0) {
        float t = 0.f;
        #pragma unroll
        for (int i = 0; i < 8; i++) t += sm[i];
        sm[0] = t;
    }
    __syncthreads();
    float r = sm[0];
    __syncthreads();
    return r;
}
__device__ __forceinline__ float pe_val(int s, int c) {
    int j = c >> 1;
    float freq = expf(-(float)(2 * j) * (9.210340371976184f / 256.0f));
    float ang = (float)s * freq;
    return (c & 1) ? cosf(ang) : sinf(ang);
}

// ---------------- shared swizzle helpers ----------------
__device__ __forceinline__ uint32_t sw_addr(uint32_t plane_base, int r, int colk) {
    int chunk = (colk >> 3) ^ ((r >> 1) & 3);
    return plane_base + r * 64 + (chunk << 4) + ((colk & 7) << 1);
}

// ============================================================
// Kernel A: 128x128 GEMM (QKV / FF1 / input-proj)
// ============================================================
#define PLANE_B 8192
#define STAGE_B 32768
#define SMEM_DYN (3*STAGE_B)   // 96 KB

__device__ __forceinline__ void issue_stage(
    uint32_t sbase, const __nv_bfloat16* __restrict__ A, size_t aps,
    const __nv_bfloat16* __restrict__ W, size_t wps,
    int row0, int col0, int K, int k0, int tid)
{
    #pragma unroll
    for (int i = 0; i < 8; i++) {
        const int plane = i >> 1;
        const int idx = ((i & 1) << 8) + tid;
        const int r = idx >> 2, c16 = idx & 3;
        const __nv_bfloat16* src = (plane < 2)
            ? A + (size_t)plane * aps + (size_t)(row0 + r) * K + (k0 + c16 * 8)
            : W + (size_t)(plane - 2) * wps + (size_t)(col0 + r) * K + (k0 + c16 * 8);
        uint32_t dst = sbase + plane * PLANE_B + r * 64 + ((c16 ^ ((r >> 1) & 3)) << 4);
        cp_async16(dst, src);
    }
}

// EPI 1: gelu -> act1 planes. EPI 2: qkvb planes. EPI 3: input-proj (PE + remap)
template <int EPI>
__global__ __launch_bounds__(256, 2)
void bfgemm_k(const __nv_bfloat16* __restrict__ A, size_t aps,
              const __nv_bfloat16* __restrict__ W, size_t wps,
              const float* __restrict__ bias,
              int M, int N, int K)
{
    extern __shared__ char smem[];
    const uint32_t sb = smem_to_u32(smem);
    const int tid = threadIdx.x;
    const int lane = tid & 31, wid = tid >> 5;
    const int row0 = blockIdx.y * 128;
    const int col0 = blockIdx.x * 128;
    const int wm0 = (wid & 1) * 64;
    const int wn0 = (wid >> 1) * 32;
    const int qr = lane >> 2, qc = lane & 3;

    const int lj = lane >> 3;
    const int lr8 = lane & 7;
    const int a_row_off = ((lj & 1) << 3) + lr8;
    const int a_k_off   = (lj >> 1) << 3;
    const int b_row_off = ((lj >> 1) << 3) + lr8;
    const int b_k_off   = (lj & 1) << 3;

    float acc[4][4][4];
    #pragma unroll
    for (int a = 0; a < 4; a++)
        #pragma unroll
        for (int b = 0; b < 4; b++)
            #pragma unroll
            for (int c = 0; c < 4; c++) acc[a][b][c] = 0.f;

    const int nk = K >> 5;

    issue_stage(sb, A, aps, W, wps, row0, col0, K, 0, tid);
    asm volatile("cp.async.commit_group;" ::: "memory");
    issue_stage(sb + STAGE_B, A, aps, W, wps, row0, col0, K, 32, tid);
    asm volatile("cp.async.commit_group;" ::: "memory");

    for (int s = 0; s < nk; s++) {
        if (s + 1 < nk) {
            asm volatile("cp.async.wait_group 1;" ::: "memory");
        } else {
            asm volatile("cp.async.wait_group 0;" ::: "memory");
        }
        __syncthreads();
        if (s + 2 < nk) {
            issue_stage(sb + ((s + 2) % 3) * STAGE_B, A, aps, W, wps, row0, col0, K, (s + 2) << 5, tid);
            asm volatile("cp.async.commit_group;" ::: "memory");
        }

        const uint32_t stg = sb + (s % 3) * STAGE_B;
        const uint32_t ah_b = stg;
        const uint32_t al_b = stg + PLANE_B;
        const uint32_t wh_b = stg + 2 * PLANE_B;
        const uint32_t wl_b = stg + 3 * PLANE_B;

        #pragma unroll
        for (int kk = 0; kk < 32; kk += 16) {
            uint32_t areg[4][4];
            uint32_t bh[4][2], bl[4][2];

            #pragma unroll
            for (int np = 0; np < 2; np++) {
                uint32_t t4[4];
                ldsm4(t4, sw_addr(wh_b, wn0 + np * 16 + b_row_off, kk + b_k_off));
                bh[np * 2][0] = t4[0]; bh[np * 2][1] = t4[1];
                bh[np * 2 + 1][0] = t4[2]; bh[np * 2 + 1][1] = t4[3];
            }
            #pragma unroll
            for (int mi = 0; mi < 4; mi++)
                ldsm4(areg[mi], sw_addr(ah_b, wm0 + mi * 16 + a_row_off, kk + a_k_off));
            #pragma unroll
            for (int mi = 0; mi < 4; mi++)
                #pragma unroll
                for (int ni = 0; ni < 4; ni++)
                    mma16816(acc[mi][ni], areg[mi], bh[ni]);
            #pragma unroll
            for (int np = 0; np < 2; np++) {
                uint32_t t4[4];
                ldsm4(t4, sw_addr(wl_b, wn0 + np * 16 + b_row_off, kk + b_k_off));
                bl[np * 2][0] = t4[0]; bl[np * 2][1] = t4[1];
                bl[np * 2 + 1][0] = t4[2]; bl[np * 2 + 1][1] = t4[3];
            }
            #pragma unroll
            for (int mi = 0; mi < 4; mi++)
                #pragma unroll
                for (int ni = 0; ni < 4; ni++)
                    mma16816(acc[mi][ni], areg[mi], bl[ni]);
            #pragma unroll
            for (int mi = 0; mi < 4; mi++)
                ldsm4(areg[mi], sw_addr(al_b, wm0 + mi * 16 + a_row_off, kk + a_k_off));
            #pragma unroll
            for (int mi = 0; mi < 4; mi++)
                #pragma unroll
                for (int ni = 0; ni < 4; ni++)
                    mma16816(acc[mi][ni], areg[mi], bh[ni]);
        }
        __syncthreads();
    }

    // ---- epilogue ----
    #pragma unroll
    for (int mi = 0; mi < 4; mi++) {
        #pragma unroll
        for (int ni = 0; ni < 4; ni++) {
            int col = col0 + wn0 + ni * 8 + qc * 2;
            float b0 = bias[col], b1 = bias[col + 1];
            #pragma unroll
            for (int half = 0; half < 2; half++) {
                int r = row0 + wm0 + mi * 16 + qr + half * 8;
                float v0 = acc[mi][ni][half * 2 + 0] + b0;
                float v1 = acc[mi][ni][half * 2 + 1] + b1;
                if (EPI == 3) {
                    int ss = r & 63, bb = r >> 6;
                    v0 += pe_val(ss, col);
                    v1 += pe_val(ss, col + 1);
                    size_t o = ((size_t)bb * Tt + 1 + ss) * Dm + col;
                    *reinterpret_cast<float2*>(&g_h[o]) = make_float2(v0, v1);
                    __nv_bfloat16 h0, l0, h1, l1;
                    split2(v0, h0, l0);
                    split2(v1, h1, l1);
                    *reinterpret_cast<__nv_bfloat162*>(&g_act0[o]) = __nv_bfloat162(h0, h1);
                    *reinterpret_cast<__nv_bfloat162*>(&g_act0[PL0 + o]) = __nv_bfloat162(l0, l1);
                } else {
                    size_t o = (size_t)r * N + col;
                    if (EPI == 1) {
                        float g0 = gelu_exact(v0), g1 = gelu_exact(v1);
                        __nv_bfloat16 h0, l0, h1, l1;
                        split2(g0, h0, l0);
                        split2(g1, h1, l1);
                        *reinterpret_cast<__nv_bfloat162*>(&g_act1[o]) = __nv_bfloat162(h0, h1);
                        *reinterpret_cast<__nv_bfloat162*>(&g_act1[PL1 + o]) = __nv_bfloat162(l0, l1);
                    } else {
                        __nv_bfloat16 h0, l0, h1, l1;
                        split2(v0, h0, l0);
                        split2(v1, h1, l1);
                        *reinterpret_cast<__nv_bfloat162*>(&g_qkvb[o]) = __nv_bfloat162(h0, h1);
                        *reinterpret_cast<__nv_bfloat162*>(&g_qkvb[PLQ + o]) = __nv_bfloat162(l0, l1);
                    }
                }
            }
        }
    }
}

// ============================================================
// Kernel B: 64x256 GEMM + residual + LayerNorm fused epilogue
// (O-proj K=256 and FF2 K=512; N = Dm = 256 always)
// ============================================================
#define LN_A_HI 0
#define LN_A_LO 4096
#define LN_W_HI 8192
#define LN_W_LO 24576
#define STAGE_LN 40960
#define SMEM_LN (2*STAGE_LN)   // 80 KB (epilogue reuses: 64*264*4 = 67.6 KB)
#define CPAD 264

__device__ __forceinline__ void issue_stage_ln(
    uint32_t sbase, const __nv_bfloat16* __restrict__ A, size_t aps,
    const __nv_bfloat16* __restrict__ W, size_t wps,
    int row0, int K, int k0, int tid)
{
    // A: 64 rows x 2 planes x 4 chunks = 512 chunks ; W: 256 x 2 x 4 = 2048
    #pragma unroll
    for (int i = 0; i < 10; i++) {
        int cid = i * 256 + tid;        // 0..2559
        const __nv_bfloat16* src;
        uint32_t pb;
        int r, c16;
        if (cid < 512) {
            int plane = cid >> 8;        // 0,1
            int j = cid & 255;
            r = j >> 2; c16 = j & 3;
            src = A + (size_t)plane * aps + (size_t)(row0 + r) * K + (k0 + c16 * 8);
            pb = sbase + (plane ? LN_A_LO : LN_A_HI);
        } else {
            int j = cid - 512;           // 0..2047
            int plane = j >> 10;         // 0,1
            j &= 1023;
            r = j >> 2; c16 = j & 3;
            src = W + (size_t)plane * wps + (size_t)r * K + (k0 + c16 * 8);
            pb = sbase + (plane ? LN_W_LO : LN_W_HI);
        }
        uint32_t dst = pb + r * 64 + ((c16 ^ ((r >> 1) & 3)) << 4);
        cp_async16(dst, src);
    }
}

__global__ __launch_bounds__(256, 2)
void bfgemm_ln_k(const __nv_bfloat16* __restrict__ A, size_t aps,
                 const __nv_bfloat16* __restrict__ W, size_t wps,
                 const float* __restrict__ bias,
                 const float* __restrict__ lng, const float* __restrict__ lnb,
                 int K)
{
    extern __shared__ char smem[];
    const uint32_t sb = smem_to_u32(smem);
    const int tid = threadIdx.x;
    const int lane = tid & 31, wid = tid >> 5;
    const int row0 = blockIdx.x * 64;
    const int wm0 = (wid & 1) * 32;
    const int wn0 = (wid >> 1) * 64;
    const int qr = lane >> 2, qc = lane & 3;

    const int lj = lane >> 3;
    const int lr8 = lane & 7;
    const int a_row_off = ((lj & 1) << 3) + lr8;
    const int a_k_off   = (lj >> 1) << 3;
    const int b_row_off = ((lj >> 1) << 3) + lr8;
    const int b_k_off   = (lj & 1) << 3;

    float acc[2][8][4];
    #pragma unroll
    for (int a = 0; a < 2; a++)
        #pragma unroll
        for (int b = 0; b < 8; b++)
            #pragma unroll
            for (int c = 0; c < 4; c++) acc[a][b][c] = 0.f;

    const int nk = K >> 5;

    issue_stage_ln(sb, A, aps, W, wps, row0, K, 0, tid);
    asm volatile("cp.async.commit_group;" ::: "memory");

    for (int s = 0; s < nk; s++) {
        if (s + 1 < nk) {
            issue_stage_ln(sb + ((s + 1) & 1) * STAGE_LN, A, aps, W, wps, row0, K, (s + 1) << 5, tid);
            asm volatile("cp.async.commit_group;" ::: "memory");
            asm volatile("cp.async.wait_group 1;" ::: "memory");
        } else {
            asm volatile("cp.async.wait_group 0;" ::: "memory");
        }
        __syncthreads();

        const uint32_t stg = sb + (s & 1) * STAGE_LN;
        const uint32_t ah_b = stg + LN_A_HI;
        const uint32_t al_b = stg + LN_A_LO;
        const uint32_t wh_b = stg + LN_W_HI;
        const uint32_t wl_b = stg + LN_W_LO;

        #pragma unroll
        for (int kk = 0; kk < 32; kk += 16) {
            uint32_t areg[2][4];
            uint32_t bh[8][2], bl[8][2];

            #pragma unroll
            for (int ng = 0; ng < 4; ng++) {
                uint32_t t4[4];
                ldsm4(t4, sw_addr(wh_b, wn0 + ng * 16 + b_row_off, kk + b_k_off));
                bh[ng * 2][0] = t4[0]; bh[ng * 2][1] = t4[1];
                bh[ng * 2 + 1][0] = t4[2]; bh[ng * 2 + 1][1] = t4[3];
            }
            #pragma unroll
            for (int mi = 0; mi < 2; mi++)
                ldsm4(areg[mi], sw_addr(ah_b, wm0 + mi * 16 + a_row_off, kk + a_k_off));
            #pragma unroll
            for (int mi = 0; mi < 2; mi++)
                #pragma unroll
                for (int ni = 0; ni < 8; ni++)
                    mma16816(acc[mi][ni], areg[mi], bh[ni]);
            #pragma unroll
            for (int ng = 0; ng < 4; ng++) {
                uint32_t t4[4];
                ldsm4(t4, sw_addr(wl_b, wn0 + ng * 16 + b_row_off, kk + b_k_off));
                bl[ng * 2][0] = t4[0]; bl[ng * 2][1] = t4[1];
                bl[ng * 2 + 1][0] = t4[2]; bl[ng * 2 + 1][1] = t4[3];
            }
            #pragma unroll
            for (int mi = 0; mi < 2; mi++)
                #pragma unroll
                for (int ni = 0; ni < 8; ni++)
                    mma16816(acc[mi][ni], areg[mi], bl[ni]);
            #pragma unroll
            for (int mi = 0; mi < 2; mi++)
                ldsm4(areg[mi], sw_addr(al_b, wm0 + mi * 16 + a_row_off, kk + a_k_off));
            #pragma unroll
            for (int mi = 0; mi < 2; mi++)
                #pragma unroll
                for (int ni = 0; ni < 8; ni++)
                    mma16816(acc[mi][ni], areg[mi], bh[ni]);
        }
        __syncthreads();
    }

    // ---- stage C (+bias+residual) into smem ----
    float* sc = reinterpret_cast<float*>(smem);
    #pragma unroll
    for (int mi = 0; mi < 2; mi++) {
        #pragma unroll
        for (int ni = 0; ni < 8; ni++) {
            int col = wn0 + ni * 8 + qc * 2;
            float b0 = bias[col], b1 = bias[col + 1];
            #pragma unroll
            for (int half = 0; half < 2; half++) {
                int rl = wm0 + mi * 16 + qr + half * 8;
                size_t go = (size_t)(row0 + rl) * Dm + col;
                float2 hv = *reinterpret_cast<const float2*>(&g_h[go]);
                sc[rl * CPAD + col]     = acc[mi][ni][half * 2 + 0] + b0 + hv.x;
                sc[rl * CPAD + col + 1] = acc[mi][ni][half * 2 + 1] + b1 + hv.y;
            }
        }
    }
    __syncthreads();

    // ---- per-row LayerNorm: warp per row, 8 rows per warp ----
    float4 gv0 = *reinterpret_cast<const float4*>(lng + lane * 8);
    float4 gv1 = *reinterpret_cast<const float4*>(lng + lane * 8 + 4);
    float4 bv0 = *reinterpret_cast<const float4*>(lnb + lane * 8);
    float4 bv1 = *reinterpret_cast<const float4*>(lnb + lane * 8 + 4);

    #pragma unroll
    for (int it = 0; it < 8; it++) {
        int rl = wid * 8 + it;
        const float* row = sc + rl * CPAD + lane * 8;
        float4 x0 = *reinterpret_cast<const float4*>(row);
        float4 x1 = *reinterpret_cast<const float4*>(row + 4);

        float s = x0.x + x0.y + x0.z + x0.w + x1.x + x1.y + x1.z + x1.w;
        #pragma unroll
        for (int o = 16; o > 0; o >>= 1) s += __shfl_xor_sync(0xffffffffu, s, o);
        float mean = s * (1.0f / Dm);

        float d0 = x0.x - mean, d1 = x0.y - mean, d2 = x0.z - mean, d3 = x0.w - mean;
        float d4 = x1.x - mean, d5 = x1.y - mean, d6 = x1.z - mean, d7 = x1.w - mean;
        float s2 = d0*d0 + d1*d1 + d2*d2 + d3*d3 + d4*d4 + d5*d5 + d6*d6 + d7*d7;
        #pragma unroll
        for (int o = 16; o > 0; o >>= 1) s2 += __shfl_xor_sync(0xffffffffu, s2, o);
        float rs = rsqrtf(s2 * (1.0f / Dm) + LN_EPS);

        float o0 = d0 * rs * gv0.x + bv0.x;
        float o1 = d1 * rs * gv0.y + bv0.y;
        float o2 = d2 * rs * gv0.z + bv0.z;
        float o3 = d3 * rs * gv0.w + bv0.w;
        float o4 = d4 * rs * gv1.x + bv1.x;
        float o5 = d5 * rs * gv1.y + bv1.y;
        float o6 = d6 * rs * gv1.z + bv1.z;
        float o7 = d7 * rs * gv1.w + bv1.w;

        size_t gbase = (size_t)(row0 + rl) * Dm + lane * 8;
        *reinterpret_cast<float4*>(&g_h[gbase])     = make_float4(o0, o1, o2, o3);
        *reinterpret_cast<float4*>(&g_h[gbase + 4]) = make_float4(o4, o5, o6, o7);

        __nv_bfloat16 h[8], l[8];
        split2(o0, h[0], l[0]); split2(o1, h[1], l[1]);
        split2(o2, h[2], l[2]); split2(o3, h[3], l[3]);
        split2(o4, h[4], l[4]); split2(o5, h[5], l[5]);
        split2(o6, h[6], l[6]); split2(o7, h[7], l[7]);
        uint4 hw, lw;
        {
            __nv_bfloat162 p0(h[0], h[1]), p1(h[2], h[3]), p2(h[4], h[5]), p3(h[6], h[7]);
            hw.x = *reinterpret_cast<uint32_t*>(&p0);
            hw.y = *reinterpret_cast<uint32_t*>(&p1);
            hw.z = *reinterpret_cast<uint32_t*>(&p2);
            hw.w = *reinterpret_cast<uint32_t*>(&p3);
            __nv_bfloat162 q0(l[0], l[1]), q1(l[2], l[3]), q2(l[4], l[5]), q3(l[6], l[7]);
            lw.x = *reinterpret_cast<uint32_t*>(&q0);
            lw.y = *reinterpret_cast<uint32_t*>(&q1);
            lw.z = *reinterpret_cast<uint32_t*>(&q2);
            lw.w = *reinterpret_cast<uint32_t*>(&q3);
        }
        *reinterpret_cast<uint4*>(&g_act0[gbase]) = hw;
        *reinterpret_cast<uint4*>(&g_act0[PL0 + gbase]) = lw;
    }
}

// ---------------- weight split ----------------
__global__ __launch_bounds__(256) void convw_k(
    const float* __restrict__ Wqkv, const float* __restrict__ Wo,
    const float* __restrict__ W1, const float* __restrict__ W2)
{
    const size_t total = (size_t)NL * WLAYER;
    for (size_t i = (size_t)blockIdx.x * blockDim.x + threadIdx.x; i < total;
         i += (size_t)gridDim.x * blockDim.x) {
        int layer = (int)(i / WLAYER);
        int off = (int)(i % WLAYER);
        float v; __nv_bfloat16 *dh, *dl;
        if (off < WQKV_SZ) {
            v = Wqkv[(size_t)layer * WQKV_SZ + off];
            dh = g_wqkvb + ((size_t)layer * 2 + 0) * WQKV_SZ + off;
            dl = g_wqkvb + ((size_t)layer * 2 + 1) * WQKV_SZ + off;
        } else if (off < WQKV_SZ + WO_SZ) {
            int o2 = off - WQKV_SZ;
            v = Wo[(size_t)layer * WO_SZ + o2];
            dh = g_wob + ((size_t)layer * 2 + 0) * WO_SZ + o2;
            dl = g_wob + ((size_t)layer * 2 + 1) * WO_SZ + o2;
        } else if (off < WQKV_SZ + WO_SZ + W1_SZ) {
            int o2 = off - WQKV_SZ - WO_SZ;
            v = W1[(size_t)layer * W1_SZ + o2];
            dh = g_w1b + ((size_t)layer * 2 + 0) * W1_SZ + o2;
            dl = g_w1b + ((size_t)layer * 2 + 1) * W1_SZ + o2;
        } else {
            int o2 = off - WQKV_SZ - WO_SZ - W1_SZ;
            v = W2[(size_t)layer * W2_SZ + o2];
            dh = g_w2b + ((size_t)layer * 2 + 0) * W2_SZ + o2;
            dl = g_w2b + ((size_t)layer * 2 + 1) * W2_SZ + o2;
        }
        __nv_bfloat16 a, b;
        split2(v, a, b);
        *dh = a; *dl = b;
    }
}

// ---------------- prep: x planes + W_in planes + cls fill ----------------
__global__ __launch_bounds__(256) void prep_k(
    const float* __restrict__ x, const float* __restrict__ W_in,
    const float* __restrict__ cls)
{
    const size_t totX = (size_t)MIN0 * KIN;
    const size_t totW = (size_t)Dm * KIN;
    const size_t totC = (size_t)Bsz * Dm;
    const size_t total = totX + totW + totC;
    for (size_t i = (size_t)blockIdx.x * blockDim.x + threadIdx.x; i < total;
         i += (size_t)gridDim.x * blockDim.x) {
        if (i < totX) {
            size_t row = i / KIN;
            int k = (int)(i % KIN);
            float v = (k < Cin) ? x[row * Cin + k] : 0.f;
            __nv_bfloat16 a, b;
            split2(v, a, b);
            g_xb[i] = a;
            g_xb[PLX + i] = b;
        } else if (i < totX + totW) {
            size_t j = i - totX;
            int row = (int)(j / KIN), k = (int)(j % KIN);
            float v = (k < Cin) ? W_in[row * Cin + k] : 0.f;
            __nv_bfloat16 a, b;
            split2(v, a, b);
            g_winb[j] = a;
            g_winb[(size_t)Dm * KIN + j] = b;
        } else {
            size_t j = i - totX - totW;
            size_t bb = j / Dm;
            int d = (int)(j % Dm);
            float v = cls[d];
            size_t idx = bb * Tt * Dm + d;
            g_h[idx] = v;
            __nv_bfloat16 hh, ll;
            split2(v, hh, ll);
            g_act0[idx] = hh;
            g_act0[PL0 + idx] = ll;
        }
    }
}

// ---------------- attention: register-blocked ----------------
#define TP 68
__global__ __launch_bounds__(256) void attn_k()
{
    const int b  = blockIdx.x >> 3;
    const int hh = blockIdx.x & 7;
    const size_t base = (size_t)b * Tt * (3 * Dm) + hh * DHd;

    __shared__ float q [TP][33];
    __shared__ float kt[TP][33];
    __shared__ float vt[TP][33];
    __shared__ float sc[TP * TP];

    const int tid = threadIdx.x;
    const int lane = tid & 31, wid = tid >> 5;

    for (int idx = tid; idx < TP * DHd; idx += 256) {
        int t = idx >> 5, d = idx & 31;
        if (t < Tt) {
            size_t o = base + (size_t)t * (3 * Dm) + d;
            q [t][d] = __bfloat162float(g_qkvb[o])          + __bfloat162float(g_qkvb[PLQ + o]);
            kt[t][d] = __bfloat162float(g_qkvb[o + Dm])     + __bfloat162float(g_qkvb[PLQ + o + Dm]);
            vt[t][d] = __bfloat162float(g_qkvb[o + 2 * Dm]) + __bfloat162float(g_qkvb[PLQ + o + 2 * Dm]);
        } else {
            q[t][d] = 0.f; kt[t][d] = 0.f; vt[t][d] = 0.f;
        }
    }
    __syncthreads();

    const float scale = 0.17677669529663689f;
    for (int tile = tid; tile < 289; tile += 256) {
        int ti = tile / 17, tj = tile - ti * 17;
        int i0 = ti << 2, j0 = tj << 2;
        float a2[4][4];
        #pragma unroll
        for (int a = 0; a < 4; a++)
            #pragma unroll
            for (int bq = 0; bq < 4; bq++) a2[a][bq] = 0.f;
        #pragma unroll 8
        for (int d = 0; d < DHd; d++) {
            float qv[4], kv[4];
            #pragma unroll
            for (int a = 0; a < 4; a++) qv[a] = q[i0 + a][d];
            #pragma unroll
            for (int bq = 0; bq < 4; bq++) kv[bq] = kt[j0 + bq][d];
            #pragma unroll
            for (int a = 0; a < 4; a++)
                #pragma unroll
                for (int bq = 0; bq < 4; bq++) a2[a][bq] += qv[a] * kv[bq];
        }
        #pragma unroll
        for (int a = 0; a < 4; a++)
            #pragma unroll
            for (int bq = 0; bq < 4; bq++)
                sc[(i0 + a) * TP + j0 + bq] = a2[a][bq] * scale;
    }
    __syncthreads();

    for (int r = wid; r < Tt; r += 8) {
        float* row = sc + r * TP;
        float e0 = row[lane];
        float e1 = row[32 + lane];
        float e2 = (lane == 0) ? row[64] : -3.4e38f;
        float m = fmaxf(fmaxf(e0, e1), e2);
        #pragma unroll
        for (int o = 16; o > 0; o >>= 1) m = fmaxf(m, __shfl_xor_sync(0xffffffffu, m, o));
        e0 = expf(e0 - m);
        e1 = expf(e1 - m);
        e2 = (lane == 0) ? expf(e2 - m) : 0.f;
        float s = e0 + e1 + e2;
        #pragma unroll
        for (int o = 16; o > 0; o >>= 1) s += __shfl_xor_sync(0xffffffffu, s, o);
        float inv = 1.0f / s;
        row[lane] = e0 * inv;
        row[32 + lane] = e1 * inv;
        if (lane == 0) row[64] = e2 * inv;
    }
    __syncthreads();

    for (int item = tid; item < 17 * 32; item += 256) {
        int ig = item >> 5, d = item & 31;
        int i0 = ig << 2;
        float o0 = 0.f, o1 = 0.f, o2 = 0.f, o3 = 0.f;
        #pragma unroll 5
        for (int j = 0; j < Tt; j++) {
            float vv = vt[j][d];
            o0 += sc[(i0 + 0) * TP + j] * vv;
            o1 += sc[(i0 + 1) * TP + j] * vv;
            o2 += sc[(i0 + 2) * TP + j] * vv;
            o3 += sc[(i0 + 3) * TP + j] * vv;
        }
        float ov[4] = {o0, o1, o2, o3};
        #pragma unroll
        for (int a = 0; a < 4; a++) {
            int i = i0 + a;
            if (i < Tt) {
                size_t oidx = ((size_t)b * Tt + i) * Dm + hh * DHd + d;
                __nv_bfloat16 h2, l2;
                split2(ov[a], h2, l2);
                g_act0[oidx] = h2;
                g_act0[PL0 + oidx] = l2;
            }
        }
    }
}

// ---------------- final head ----------------
__global__ __launch_bounds__(256) void final_head_k(
    const float* __restrict__ lnfg, const float* __restrict__ lnfb,
    const float* __restrict__ Wout, const float* __restrict__ bout)
{
    __shared__ float xn[Dm];
    __shared__ float sm[32];
    const int tid = threadIdx.x;
    const int b = blockIdx.x;
    float v = g_h[(size_t)b * Tt * Dm + tid];
    float mean = bred256(v, sm) * (1.0f / Dm);
    float d = v - mean;
    float var = bred256(d * d, sm) * (1.0f / Dm);
    xn[tid] = d * rsqrtf(var + LN_EPS) * lnfg[tid] + lnfb[tid];
    __syncthreads();
    if (tid < Ed) {
        const float* w = Wout + (size_t)tid * Dm;
        float a = bout[tid];
        #pragma unroll 8
        for (int t = 0; t < Dm; t++) a += xn[t] * w[t];
        g_ze[(size_t)b * Ed + tid] = a;
    }
}

// ---------------- codebook norms + hist zero ----------------
__global__ __launch_bounds__(128) void cnorm_k(const float* __restrict__ cb) {
    __shared__ float sm[4];
    const int tid = threadIdx.x;
    float v = cb[(size_t)blockIdx.x * Ed + tid];
    v *= v;
    #pragma unroll
    for (int o = 16; o > 0; o >>= 1) v += __shfl_down_sync(0xffffffffu, v, o);
    if ((tid & 31) == 0) sm[tid >> 5] = v;
    __syncthreads();
    if (tid == 0) {
        g_cnorm[blockIdx.x] = sm[0] + sm[1] + sm[2] + sm[3];
        g_hist[blockIdx.x] = 0;
    }
}

// ---------------- VQ ----------------
__global__ __launch_bounds__(256) void vq_k(const float* __restrict__ cb) {
    __shared__ float ze[Ed];
    __shared__ float bm[256];
    __shared__ int   bi[256];
    __shared__ int   chosen;
    __shared__ float sm[32];
    const int tid = threadIdx.x;
    const int b = blockIdx.x;
    if (tid < Ed) ze[tid] = g_ze[(size_t)b * Ed + tid];
    __syncthreads();

    float best = 3.4e38f;
    int besti = 0x7fffffff;
    for (int k = tid; k < Kcb; k += 256) {
        const float* c = cb + (size_t)k * Ed;
        float dot = 0.f;
        #pragma unroll 4
        for (int e = 0; e < Ed; e++) dot += ze[e] * c[e];
        float dd = g_cnorm[k] - 2.0f * dot;
        if (dd < best || (dd == best && k < besti)) { best = dd; besti = k; }
    }
    bm[tid] = best; bi[tid] = besti;
    __syncthreads();
    for (int off = 128; off > 0; off >>= 1) {
        if (tid < off) {
            float ob = bm[tid + off]; int oi = bi[tid + off];
            if (ob < bm[tid] || (ob == bm[tid] && oi < bi[tid])) { bm[tid] = ob; bi[tid] = oi; }
        }
        __syncthreads();
    }
    if (tid == 0) {
        chosen = bi[0];
        g_idx[b] = bi[0];
        atomicAdd(&g_hist[bi[0]], 1);
    }
    __syncthreads();

    const int kk = chosen;
    float part = 0.f;
    if (tid < Ed) {
        float diff = cb[(size_t)kk * Ed + tid] - ze[tid];
        part = diff * diff;
    }
    float tot = bred256(part, sm);
    if (tid == 0) g_losspart[b] = tot;
}

// ---------------- decoder ----------------
__global__ __launch_bounds__(256) void decoder_k(
    const float* __restrict__ cb,
    const float* __restrict__ Wd1, const float* __restrict__ bd1,
    const float* __restrict__ lndg, const float* __restrict__ lndb,
    const float* __restrict__ Wd2, const float* __restrict__ bd2,
    const float* __restrict__ Wd3, const float* __restrict__ bd3,
    float* __restrict__ outp)
{
    __shared__ float zq[Ed];
    __shared__ float d1[Dm];
    __shared__ float d2s[Ed];
    __shared__ float sm[32];
    const int tid = threadIdx.x;
    const int b = blockIdx.x;
    const int ci = g_idx[b];
    if (tid < Ed) zq[tid] = cb[(size_t)ci * Ed + tid];
    __syncthreads();

    float t1 = bd1[tid];
    {
        const float* w = Wd1 + (size_t)tid * Ed;
        #pragma unroll 4
        for (int e = 0; e < Ed; e++) t1 += zq[e] * w[e];
    }
    float mean = bred256(t1, sm) * (1.0f / Dm);
    float dd = t1 - mean;
    float var = bred256(dd * dd, sm) * (1.0f / Dm);
    float xg = dd * rsqrtf(var + LN_EPS) * lndg[tid] + lndb[tid];
    d1[tid] = gelu_exact(xg);
    __syncthreads();

    if (tid < Ed) {
        const float* w2 = Wd2 + (size_t)tid * Dm;
        float t2 = bd2[tid];
        #pragma unroll 8
        for (int t = 0; t < Dm; t++) t2 += d1[t] * w2[t];
        d2s[tid] = gelu_exact(t2);
    }
    __syncthreads();

    if (tid < 2) {
        const float* w3 = Wd3 + (size_t)tid * Ed;
        float vv = bd3[tid];
        #pragma unroll 4
        for (int e = 0; e < Ed; e++) vv += d2s[e] * w3[e];
        outp[(size_t)b * 2 + tid] = vv;
    }
    if (tid == 2) outp[(size_t)Bsz * 2 + b] = (float)ci;
}

// ---------------- scalars ----------------
__global__ __launch_bounds__(1024) void scalars_k(float* __restrict__ outp) {
    __shared__ float sm[32];
    const int tid = threadIdx.x;

    float p = (float)g_hist[tid] * (1.0f / (float)Bsz);
    float term = p * logf(p + 1e-10f);
    float v = term;
    #pragma unroll
    for (int o = 16; o > 0; o >>= 1) v += __shfl_down_sync(0xffffffffu, v, o);
    if ((tid & 31) == 0) sm[tid >> 5] = v;
    __syncthreads();
    float ent = 0.f;
    if (tid == 0) {
        for (int i = 0; i < 32; i++) ent += sm[i];
        sm[0] = ent;
    }
    __syncthreads();
    ent = sm[0];
    __syncthreads();

    float lp = g_losspart[tid] + g_losspart[tid + 1024];
    #pragma unroll
    for (int o = 16; o > 0; o >>= 1) lp += __shfl_down_sync(0xffffffffu, lp, o);
    if ((tid & 31) == 0) sm[tid >> 5] = lp;
    __syncthreads();
    if (tid == 0) {
        float tot = 0.f;
        for (int i = 0; i < 32; i++) tot += sm[i];
        outp[(size_t)Bsz * 2 + Bsz + 0] = 0.1f * tot / ((float)Bsz * (float)Ed);
        outp[(size_t)Bsz * 2 + Bsz + 1] = expf(-ent);
    }
}

// ---------------- host ----------------
template <typename T>
static T* sym_addr(const void* sym) {
    void* p = nullptr;
    cudaGetSymbolAddress(&p, sym);
    return (T*)p;
}

extern "C" void kernel_launch(void* const* d_in, const int* in_sizes, int n_in,
                              void* d_out, int out_size)
{
    (void)in_sizes; (void)n_in; (void)out_size;
    const float* x     = (const float*)d_in[0];
    const float* W_in  = (const float*)d_in[1];
    const float* b_in  = (const float*)d_in[2];
    const float* cls   = (const float*)d_in[3];
    const float* Wqkv  = (const float*)d_in[4];
    const float* bqkv  = (const float*)d_in[5];
    const float* Wo    = (const float*)d_in[6];
    const float* bo    = (const float*)d_in[7];
    const float* W1    = (const float*)d_in[8];
    const float* b1    = (const float*)d_in[9];
    const float* W2    = (const float*)d_in[10];
    const float* b2    = (const float*)d_in[11];
    const float* ln1g  = (const float*)d_in[12];
    const float* ln1b  = (const float*)d_in[13];
    const float* ln2g  = (const float*)d_in[14];
    const float* ln2b  = (const float*)d_in[15];
    const float* lnfg  = (const float*)d_in[16];
    const float* lnfb  = (const float*)d_in[17];
    const float* Wout  = (const float*)d_in[18];
    const float* bout  = (const float*)d_in[19];
    const float* cb    = (const float*)d_in[20];
    const float* Wd1   = (const float*)d_in[21];
    const float* bd1   = (const float*)d_in[22];
    const float* lndg  = (const float*)d_in[23];
    const float* lndb  = (const float*)d_in[24];
    const float* Wd2   = (const float*)d_in[25];
    const float* bd2   = (const float*)d_in[26];
    const float* Wd3   = (const float*)d_in[27];
    const float* bd3   = (const float*)d_in[28];
    float* outp = (float*)d_out;

    __nv_bfloat16* pAct0 = sym_addr<__nv_bfloat16>(g_act0);
    __nv_bfloat16* pAct1 = sym_addr<__nv_bfloat16>(g_act1);
    __nv_bfloat16* pXb   = sym_addr<__nv_bfloat16>(g_xb);
    __nv_bfloat16* pWin  = sym_addr<__nv_bfloat16>(g_winb);
    __nv_bfloat16* pWq = sym_addr<__nv_bfloat16>(g_wqkvb);
    __nv_bfloat16* pWo = sym_addr<__nv_bfloat16>(g_wob);
    __nv_bfloat16* pW1 = sym_addr<__nv_bfloat16>(g_w1b);
    __nv_bfloat16* pW2 = sym_addr<__nv_bfloat16>(g_w2b);

    cudaFuncSetAttribute(bfgemm_k<1>, cudaFuncAttributeMaxDynamicSharedMemorySize, SMEM_DYN);
    cudaFuncSetAttribute(bfgemm_k<2>, cudaFuncAttributeMaxDynamicSharedMemorySize, SMEM_DYN);
    cudaFuncSetAttribute(bfgemm_k<3>, cudaFuncAttributeMaxDynamicSharedMemorySize, SMEM_DYN);
    cudaFuncSetAttribute(bfgemm_ln_k, cudaFuncAttributeMaxDynamicSharedMemorySize, SMEM_LN);

    convw_k<<<1024, 256>>>(Wqkv, Wo, W1, W2);                       // 1
    prep_k<<<2048, 256>>>(x, W_in, cls);                            // 2
    bfgemm_k<3><<<dim3(Dm / 128, MIN0 / 128), 256, SMEM_DYN>>>(
        pXb, PLX, pWin, (size_t)Dm * KIN, b_in, MIN0, Dm, KIN);     // 3

    for (int i = 0; i < NL; i++) {
        bfgemm_k<2><<<dim3(768 / 128, MTOK / 128), 256, SMEM_DYN>>>(
            pAct0, PL0, pWq + (size_t)i * 2 * WQKV_SZ, (size_t)WQKV_SZ,
            bqkv + (size_t)i * 3 * Dm, MTOK, 3 * Dm, Dm);           // 4 on i=0
        attn_k<<<Bsz * NH, 256>>>();
        bfgemm_ln_k<<<MTOK / 64, 256, SMEM_LN>>>(
            pAct0, PL0, pWo + (size_t)i * 2 * WO_SZ, (size_t)WO_SZ,
            bo + (size_t)i * Dm, ln1g + (size_t)i * Dm, ln1b + (size_t)i * Dm, Dm);
        bfgemm_k<1><<<dim3(FFd / 128, MTOK / 128), 256, SMEM_DYN>>>(
            pAct0, PL0, pW1 + (size_t)i * 2 * W1_SZ, (size_t)W1_SZ,
            b1 + (size_t)i * FFd, MTOK, FFd, Dm);
        bfgemm_ln_k<<<MTOK / 64, 256, SMEM_LN>>>(
            pAct1, PL1, pW2 + (size_t)i * 2 * W2_SZ, (size_t)W2_SZ,
            b2 + (size_t)i * Dm, ln2g + (size_t)i * Dm, ln2b + (size_t)i * Dm, FFd);
    }

    cnorm_k<<<Kcb, 128>>>(cb);
    final_head_k<<<Bsz, 256>>>(lnfg, lnfb, Wout, bout);
    vq_k<<<Bsz, 256>>>(cb);
    decoder_k<<<Bsz, 256>>>(cb, Wd1, bd1, lndg, lndb, Wd2, bd2, Wd3, bd3, outp);
    scalars_k<<<1, 1024>>>(outp);
}

// round 14
// speedup vs baseline: 1.5391x; 1.5391x over previous
#include <cuda_runtime.h>
#include <cuda_bf16.h>
#include <math.h>
#include <stdint.h>

// ---------------- problem constants ----------------
#define Bsz 2048
#define Ssz 64
#define Cin 142
#define KIN 160
#define Dm  256
#define NH  8
#define DHd 32
#define FFd 512
#define NL  3
#define Ed  128
#define Kcb 1024
#define Tt  65
#define MTOK (Bsz*Tt)
#define MIN0 (Bsz*Ssz)
#define LN_EPS 1e-5f

#define PL0 ((size_t)MTOK*Dm)
#define PL1 ((size_t)MTOK*FFd)
#define PLQ ((size_t)MTOK*3*Dm)
#define PLX ((size_t)MIN0*KIN)
#define WQKV_SZ (3*Dm*Dm)
#define WO_SZ   (Dm*Dm)
#define W1_SZ   (FFd*Dm)
#define W2_SZ   (Dm*FFd)
#define WLAYER  (WQKV_SZ+WO_SZ+W1_SZ+W2_SZ)

// ---------------- scratch ----------------
__device__ float g_h   [(size_t)Bsz*Tt*Dm];
__device__ float g_tmp [(size_t)Bsz*Tt*Dm];
__device__ float g_ze  [(size_t)Bsz*Ed];
__device__ int   g_idx [Bsz];
__device__ float g_cnorm[Kcb];
__device__ int   g_hist[Kcb];
__device__ float g_losspart[Bsz];

__device__ __nv_bfloat16 g_act0[2*PL0];
__device__ __nv_bfloat16 g_act1[2*PL1];
__device__ __nv_bfloat16 g_qkvb[2*PLQ];
__device__ __nv_bfloat16 g_xb  [2*PLX];
__device__ __nv_bfloat16 g_winb[2*Dm*KIN];
__device__ __nv_bfloat16 g_wqkvb[(size_t)NL*2*WQKV_SZ];
__device__ __nv_bfloat16 g_wob  [(size_t)NL*2*WO_SZ];
__device__ __nv_bfloat16 g_w1b  [(size_t)NL*2*W1_SZ];
__device__ __nv_bfloat16 g_w2b  [(size_t)NL*2*W2_SZ];

// ---------------- low-level helpers ----------------
__device__ __forceinline__ uint32_t smem_to_u32(const void* p) {
    uint32_t a;
    asm("{ .reg .u64 t; cvta.to.shared.u64 t, %1; cvt.u32.u64 %0, t; }" : "=r"(a) : "l"(p));
    return a;
}
__device__ __forceinline__ void cp_async16(uint32_t saddr, const void* gaddr) {
    asm volatile("cp.async.cg.shared.global [%0], [%1], 16;" :: "r"(saddr), "l"(gaddr));
}
__device__ __forceinline__ void ldsm4(uint32_t* r, uint32_t addr) {
    asm volatile("ldmatrix.sync.aligned.m8n8.x4.shared.b16 {%0,%1,%2,%3}, [%4];"
        : "=r"(r[0]), "=r"(r[1]), "=r"(r[2]), "=r"(r[3]) : "r"(addr));
}
__device__ __forceinline__ void mma16816(float* c, const uint32_t* a, const uint32_t* b) {
    asm volatile(
        "mma.sync.aligned.m16n8k16.row.col.f32.bf16.bf16.f32 "
        "{%0,%1,%2,%3}, {%4,%5,%6,%7}, {%8,%9}, {%0,%1,%2,%3};"
        : "+f"(c[0]), "+f"(c[1]), "+f"(c[2]), "+f"(c[3])
        : "r"(a[0]), "r"(a[1]), "r"(a[2]), "r"(a[3]), "r"(b[0]), "r"(b[1]));
}
__device__ __forceinline__ float gelu_exact(float x) {
    return 0.5f * x * (1.0f + erff(x * 0.7071067811865475f));
}
__device__ __forceinline__ void split2(float v, __nv_bfloat16& h, __nv_bfloat16& l) {
    h = __float2bfloat16(v);
    l = __float2bfloat16(v - __bfloat162float(h));
}
__device__ __forceinline__ float bred256(float v, float* sm) {
    int tid = threadIdx.x;
    #pragma unroll
    for (int o = 16; o > 0; o >>= 1) v += __shfl_down_sync(0xffffffffu, v, o);
    if ((tid & 31) == 0) sm[tid >> 5] = v;
    __syncthreads();
    if (tid == 0) {
        float t = 0.f;
        #pragma unroll
        for (int i = 0; i < 8; i++) t += sm[i];
        sm[0] = t;
    }
    __syncthreads();
    float r = sm[0];
    __syncthreads();
    return r;
}
__device__ __forceinline__ float pe_val(int s, int c) {
    int j = c >> 1;
    float freq = expf(-(float)(2 * j) * (9.210340371976184f / 256.0f));
    float ang = (float)s * freq;
    return (c & 1) ? cosf(ang) : sinf(ang);
}

// ---------------- mma.sync bf16 2-split (3-term) GEMM ----------------
#define PLANE_B 8192
#define STAGE_B 32768
#define SMEM_DYN (3*STAGE_B)   // 96 KB

__device__ __forceinline__ uint32_t sw_addr(uint32_t plane_base, int r, int colk) {
    int chunk = (colk >> 3) ^ ((r >> 1) & 3);
    return plane_base + r * 64 + (chunk << 4) + ((colk & 7) << 1);
}

__device__ __forceinline__ void issue_stage(
    uint32_t sbase, const __nv_bfloat16* __restrict__ A, size_t aps,
    const __nv_bfloat16* __restrict__ W, size_t wps,
    int row0, int col0, int K, int k0, int tid)
{
    #pragma unroll
    for (int i = 0; i < 8; i++) {
        const int plane = i >> 1;
        const int idx = ((i & 1) << 8) + tid;
        const int r = idx >> 2, c16 = idx & 3;
        const __nv_bfloat16* src = (plane < 2)
            ? A + (size_t)plane * aps + (size_t)(row0 + r) * K + (k0 + c16 * 8)
            : W + (size_t)(plane - 2) * wps + (size_t)(col0 + r) * K + (k0 + c16 * 8);
        uint32_t dst = sbase + plane * PLANE_B + r * 64 + ((c16 ^ ((r >> 1) & 3)) << 4);
        cp_async16(dst, src);
    }
}

// EPI 0: residual (reads g_h) + fp32 to C. EPI 1: gelu -> act1 planes.
// EPI 2: qkvb planes. EPI 3: input-proj (PE + remap -> g_h + act0 planes)
template <int EPI>
__global__ __launch_bounds__(256, 2)
void bfgemm_k(const __nv_bfloat16* __restrict__ A, size_t aps,
              const __nv_bfloat16* __restrict__ W, size_t wps,
              const float* __restrict__ bias, float* __restrict__ C,
              int M, int N, int K)
{
    extern __shared__ char smem[];
    const uint32_t sb = smem_to_u32(smem);
    const int tid = threadIdx.x;
    const int lane = tid & 31, wid = tid >> 5;
    const int row0 = blockIdx.y * 128;
    const int col0 = blockIdx.x * 128;
    const int wm0 = (wid & 1) * 64;
    const int wn0 = (wid >> 1) * 32;
    const int qr = lane >> 2, qc = lane & 3;

    const int lj = lane >> 3;
    const int lr8 = lane & 7;
    const int a_row_off = ((lj & 1) << 3) + lr8;
    const int a_k_off   = (lj >> 1) << 3;
    const int b_row_off = ((lj >> 1) << 3) + lr8;
    const int b_k_off   = (lj & 1) << 3;

    float acc[4][4][4];
    #pragma unroll
    for (int a = 0; a < 4; a++)
        #pragma unroll
        for (int b = 0; b < 4; b++)
            #pragma unroll
            for (int c = 0; c < 4; c++) acc[a][b][c] = 0.f;

    const int nk = K >> 5;

    issue_stage(sb, A, aps, W, wps, row0, col0, K, 0, tid);
    asm volatile("cp.async.commit_group;" ::: "memory");
    issue_stage(sb + STAGE_B, A, aps, W, wps, row0, col0, K, 32, tid);
    asm volatile("cp.async.commit_group;" ::: "memory");

    for (int s = 0; s < nk; s++) {
        if (s + 1 < nk) {
            asm volatile("cp.async.wait_group 1;" ::: "memory");
        } else {
            asm volatile("cp.async.wait_group 0;" ::: "memory");
        }
        __syncthreads();
        if (s + 2 < nk) {
            issue_stage(sb + ((s + 2) % 3) * STAGE_B, A, aps, W, wps, row0, col0, K, (s + 2) << 5, tid);
            asm volatile("cp.async.commit_group;" ::: "memory");
        }

        const uint32_t stg = sb + (s % 3) * STAGE_B;
        const uint32_t ah_b = stg;
        const uint32_t al_b = stg + PLANE_B;
        const uint32_t wh_b = stg + 2 * PLANE_B;
        const uint32_t wl_b = stg + 3 * PLANE_B;

        #pragma unroll
        for (int kk = 0; kk < 32; kk += 16) {
            uint32_t areg[4][4];
            uint32_t bh[4][2], bl[4][2];

            #pragma unroll
            for (int np = 0; np < 2; np++) {
                uint32_t t4[4];
                ldsm4(t4, sw_addr(wh_b, wn0 + np * 16 + b_row_off, kk + b_k_off));
                bh[np * 2][0] = t4[0]; bh[np * 2][1] = t4[1];
                bh[np * 2 + 1][0] = t4[2]; bh[np * 2 + 1][1] = t4[3];
            }
            #pragma unroll
            for (int mi = 0; mi < 4; mi++)
                ldsm4(areg[mi], sw_addr(ah_b, wm0 + mi * 16 + a_row_off, kk + a_k_off));
            #pragma unroll
            for (int mi = 0; mi < 4; mi++)
                #pragma unroll
                for (int ni = 0; ni < 4; ni++)
                    mma16816(acc[mi][ni], areg[mi], bh[ni]);
            #pragma unroll
            for (int np = 0; np < 2; np++) {
                uint32_t t4[4];
                ldsm4(t4, sw_addr(wl_b, wn0 + np * 16 + b_row_off, kk + b_k_off));
                bl[np * 2][0] = t4[0]; bl[np * 2][1] = t4[1];
                bl[np * 2 + 1][0] = t4[2]; bl[np * 2 + 1][1] = t4[3];
            }
            #pragma unroll
            for (int mi = 0; mi < 4; mi++)
                #pragma unroll
                for (int ni = 0; ni < 4; ni++)
                    mma16816(acc[mi][ni], areg[mi], bl[ni]);
            #pragma unroll
            for (int mi = 0; mi < 4; mi++)
                ldsm4(areg[mi], sw_addr(al_b, wm0 + mi * 16 + a_row_off, kk + a_k_off));
            #pragma unroll
            for (int mi = 0; mi < 4; mi++)
                #pragma unroll
                for (int ni = 0; ni < 4; ni++)
                    mma16816(acc[mi][ni], areg[mi], bh[ni]);
        }
        __syncthreads();
    }

    // ---- epilogue ----
    #pragma unroll
    for (int mi = 0; mi < 4; mi++) {
        #pragma unroll
        for (int ni = 0; ni < 4; ni++) {
            int col = col0 + wn0 + ni * 8 + qc * 2;
            float b0 = bias[col], b1 = bias[col + 1];
            #pragma unroll
            for (int half = 0; half < 2; half++) {
                int r = row0 + wm0 + mi * 16 + qr + half * 8;
                float v0 = acc[mi][ni][half * 2 + 0] + b0;
                float v1 = acc[mi][ni][half * 2 + 1] + b1;
                if (EPI == 3) {
                    int ss = r & 63, bb = r >> 6;
                    v0 += pe_val(ss, col);
                    v1 += pe_val(ss, col + 1);
                    size_t o = ((size_t)bb * Tt + 1 + ss) * Dm + col;
                    *reinterpret_cast<float2*>(&g_h[o]) = make_float2(v0, v1);
                    __nv_bfloat16 h0, l0, h1, l1;
                    split2(v0, h0, l0);
                    split2(v1, h1, l1);
                    *reinterpret_cast<__nv_bfloat162*>(&g_act0[o]) = __nv_bfloat162(h0, h1);
                    *reinterpret_cast<__nv_bfloat162*>(&g_act0[PL0 + o]) = __nv_bfloat162(l0, l1);
                } else {
                    size_t o = (size_t)r * N + col;
                    if (EPI == 0) {
                        float2 hv = *reinterpret_cast<const float2*>(&g_h[o]);
                        *reinterpret_cast<float2*>(C + o) = make_float2(v0 + hv.x, v1 + hv.y);
                    } else if (EPI == 1) {
                        float g0 = gelu_exact(v0), g1 = gelu_exact(v1);
                        __nv_bfloat16 h0, l0, h1, l1;
                        split2(g0, h0, l0);
                        split2(g1, h1, l1);
                        *reinterpret_cast<__nv_bfloat162*>(&g_act1[o]) = __nv_bfloat162(h0, h1);
                        *reinterpret_cast<__nv_bfloat162*>(&g_act1[PL1 + o]) = __nv_bfloat162(l0, l1);
                    } else {
                        __nv_bfloat16 h0, l0, h1, l1;
                        split2(v0, h0, l0);
                        split2(v1, h1, l1);
                        *reinterpret_cast<__nv_bfloat162*>(&g_qkvb[o]) = __nv_bfloat162(h0, h1);
                        *reinterpret_cast<__nv_bfloat162*>(&g_qkvb[PLQ + o]) = __nv_bfloat162(l0, l1);
                    }
                }
            }
        }
    }
}

// ---------------- weight split ----------------
__global__ __launch_bounds__(256) void convw_k(
    const float* __restrict__ Wqkv, const float* __restrict__ Wo,
    const float* __restrict__ W1, const float* __restrict__ W2)
{
    const size_t total = (size_t)NL * WLAYER;
    for (size_t i = (size_t)blockIdx.x * blockDim.x + threadIdx.x; i < total;
         i += (size_t)gridDim.x * blockDim.x) {
        int layer = (int)(i / WLAYER);
        int off = (int)(i % WLAYER);
        float v; __nv_bfloat16 *dh, *dl;
        if (off < WQKV_SZ) {
            v = Wqkv[(size_t)layer * WQKV_SZ + off];
            dh = g_wqkvb + ((size_t)layer * 2 + 0) * WQKV_SZ + off;
            dl = g_wqkvb + ((size_t)layer * 2 + 1) * WQKV_SZ + off;
        } else if (off < WQKV_SZ + WO_SZ) {
            int o2 = off - WQKV_SZ;
            v = Wo[(size_t)layer * WO_SZ + o2];
            dh = g_wob + ((size_t)layer * 2 + 0) * WO_SZ + o2;
            dl = g_wob + ((size_t)layer * 2 + 1) * WO_SZ + o2;
        } else if (off < WQKV_SZ + WO_SZ + W1_SZ) {
            int o2 = off - WQKV_SZ - WO_SZ;
            v = W1[(size_t)layer * W1_SZ + o2];
            dh = g_w1b + ((size_t)layer * 2 + 0) * W1_SZ + o2;
            dl = g_w1b + ((size_t)layer * 2 + 1) * W1_SZ + o2;
        } else {
            int o2 = off - WQKV_SZ - WO_SZ - W1_SZ;
            v = W2[(size_t)layer * W2_SZ + o2];
            dh = g_w2b + ((size_t)layer * 2 + 0) * W2_SZ + o2;
            dl = g_w2b + ((size_t)layer * 2 + 1) * W2_SZ + o2;
        }
        __nv_bfloat16 a, b;
        split2(v, a, b);
        *dh = a; *dl = b;
    }
}

// ---------------- prep: x planes + W_in planes + cls fill ----------------
__global__ __launch_bounds__(256) void prep_k(
    const float* __restrict__ x, const float* __restrict__ W_in,
    const float* __restrict__ cls)
{
    const size_t totX = (size_t)MIN0 * KIN;
    const size_t totW = (size_t)Dm * KIN;
    const size_t totC = (size_t)Bsz * Dm;
    const size_t total = totX + totW + totC;
    for (size_t i = (size_t)blockIdx.x * blockDim.x + threadIdx.x; i < total;
         i += (size_t)gridDim.x * blockDim.x) {
        if (i < totX) {
            size_t row = i / KIN;
            int k = (int)(i % KIN);
            float v = (k < Cin) ? x[row * Cin + k] : 0.f;
            __nv_bfloat16 a, b;
            split2(v, a, b);
            g_xb[i] = a;
            g_xb[PLX + i] = b;
        } else if (i < totX + totW) {
            size_t j = i - totX;
            int row = (int)(j / KIN), k = (int)(j % KIN);
            float v = (k < Cin) ? W_in[row * Cin + k] : 0.f;
            __nv_bfloat16 a, b;
            split2(v, a, b);
            g_winb[j] = a;
            g_winb[(size_t)Dm * KIN + j] = b;
        } else {
            size_t j = i - totX - totW;
            size_t bb = j / Dm;
            int d = (int)(j % Dm);
            float v = cls[d];
            size_t idx = bb * Tt * Dm + d;
            g_h[idx] = v;
            __nv_bfloat16 hh, ll;
            split2(v, hh, ll);
            g_act0[idx] = hh;
            g_act0[PL0 + idx] = ll;
        }
    }
}

// ---------------- attention: register-blocked ----------------
#define TP 68
__global__ __launch_bounds__(256) void attn_k()
{
    const int b  = blockIdx.x >> 3;
    const int hh = blockIdx.x & 7;
    const size_t base = (size_t)b * Tt * (3 * Dm) + hh * DHd;

    __shared__ float q [TP][33];
    __shared__ float kt[TP][33];
    __shared__ float vt[TP][33];
    __shared__ float sc[TP * TP];

    const int tid = threadIdx.x;
    const int lane = tid & 31, wid = tid >> 5;

    for (int idx = tid; idx < TP * DHd; idx += 256) {
        int t = idx >> 5, d = idx & 31;
        if (t < Tt) {
            size_t o = base + (size_t)t * (3 * Dm) + d;
            q [t][d] = __bfloat162float(g_qkvb[o])          + __bfloat162float(g_qkvb[PLQ + o]);
            kt[t][d] = __bfloat162float(g_qkvb[o + Dm])     + __bfloat162float(g_qkvb[PLQ + o + Dm]);
            vt[t][d] = __bfloat162float(g_qkvb[o + 2 * Dm]) + __bfloat162float(g_qkvb[PLQ + o + 2 * Dm]);
        } else {
            q[t][d] = 0.f; kt[t][d] = 0.f; vt[t][d] = 0.f;
        }
    }
    __syncthreads();

    const float scale = 0.17677669529663689f;
    for (int tile = tid; tile < 289; tile += 256) {
        int ti = tile / 17, tj = tile - ti * 17;
        int i0 = ti << 2, j0 = tj << 2;
        float a2[4][4];
        #pragma unroll
        for (int a = 0; a < 4; a++)
            #pragma unroll
            for (int bq = 0; bq < 4; bq++) a2[a][bq] = 0.f;
        #pragma unroll 8
        for (int d = 0; d < DHd; d++) {
            float qv[4], kv[4];
            #pragma unroll
            for (int a = 0; a < 4; a++) qv[a] = q[i0 + a][d];
            #pragma unroll
            for (int bq = 0; bq < 4; bq++) kv[bq] = kt[j0 + bq][d];
            #pragma unroll
            for (int a = 0; a < 4; a++)
                #pragma unroll
                for (int bq = 0; bq < 4; bq++) a2[a][bq] += qv[a] * kv[bq];
        }
        #pragma unroll
        for (int a = 0; a < 4; a++)
            #pragma unroll
            for (int bq = 0; bq < 4; bq++)
                sc[(i0 + a) * TP + j0 + bq] = a2[a][bq] * scale;
    }
    __syncthreads();

    for (int r = wid; r < Tt; r += 8) {
        float* row = sc + r * TP;
        float e0 = row[lane];
        float e1 = row[32 + lane];
        float e2 = (lane == 0) ? row[64] : -3.4e38f;
        float m = fmaxf(fmaxf(e0, e1), e2);
        #pragma unroll
        for (int o = 16; o > 0; o >>= 1) m = fmaxf(m, __shfl_xor_sync(0xffffffffu, m, o));
        e0 = expf(e0 - m);
        e1 = expf(e1 - m);
        e2 = (lane == 0) ? expf(e2 - m) : 0.f;
        float s = e0 + e1 + e2;
        #pragma unroll
        for (int o = 16; o > 0; o >>= 1) s += __shfl_xor_sync(0xffffffffu, s, o);
        float inv = 1.0f / s;
        row[lane] = e0 * inv;
        row[32 + lane] = e1 * inv;
        if (lane == 0) row[64] = e2 * inv;
    }
    __syncthreads();

    for (int item = tid; item < 17 * 32; item += 256) {
        int ig = item >> 5, d = item & 31;
        int i0 = ig << 2;
        float o0 = 0.f, o1 = 0.f, o2 = 0.f, o3 = 0.f;
        #pragma unroll 5
        for (int j = 0; j < Tt; j++) {
            float vv = vt[j][d];
            o0 += sc[(i0 + 0) * TP + j] * vv;
            o1 += sc[(i0 + 1) * TP + j] * vv;
            o2 += sc[(i0 + 2) * TP + j] * vv;
            o3 += sc[(i0 + 3) * TP + j] * vv;
        }
        float ov[4] = {o0, o1, o2, o3};
        #pragma unroll
        for (int a = 0; a < 4; a++) {
            int i = i0 + a;
            if (i < Tt) {
                size_t oidx = ((size_t)b * Tt + i) * Dm + hh * DHd + d;
                __nv_bfloat16 h2, l2;
                split2(ov[a], h2, l2);
                g_act0[oidx] = h2;
                g_act0[PL0 + oidx] = l2;
            }
        }
    }
}

// ---------------- LayerNorm (input presummed in t), writes h + planes ----------------
__global__ __launch_bounds__(256) void add_ln_k(
    float* __restrict__ h, const float* __restrict__ t,
    const float* __restrict__ g, const float* __restrict__ bb)
{
    __shared__ float sms[8];
    const int tid = threadIdx.x;
    const int grp = tid >> 6;
    const int lt  = tid & 63;
    const int wid = tid >> 5;
    const size_t row = (size_t)blockIdx.x * 4 + grp;
    const size_t base = row * Dm + lt * 4;

    float4 tv = *reinterpret_cast<const float4*>(t + base);
    float v0 = tv.x, v1 = tv.y, v2 = tv.z, v3 = tv.w;

    float s = v0 + v1 + v2 + v3;
    #pragma unroll
    for (int o = 16; o > 0; o >>= 1) s += __shfl_down_sync(0xffffffffu, s, o);
    if ((tid & 31) == 0) sms[wid] = s;
    __syncthreads();
    float mean = (sms[grp * 2] + sms[grp * 2 + 1]) * (1.0f / Dm);
    __syncthreads();

    float d0 = v0 - mean, d1 = v1 - mean, d2 = v2 - mean, d3 = v3 - mean;
    float s2 = d0 * d0 + d1 * d1 + d2 * d2 + d3 * d3;
    #pragma unroll
    for (int o = 16; o > 0; o >>= 1) s2 += __shfl_down_sync(0xffffffffu, s2, o);
    if ((tid & 31) == 0) sms[wid] = s2;
    __syncthreads();
    float var = (sms[grp * 2] + sms[grp * 2 + 1]) * (1.0f / Dm);
    float rs = rsqrtf(var + LN_EPS);

    float4 gv = *reinterpret_cast<const float4*>(g + lt * 4);
    float4 bv = *reinterpret_cast<const float4*>(bb + lt * 4);
    float o0 = d0 * rs * gv.x + bv.x;
    float o1 = d1 * rs * gv.y + bv.y;
    float o2 = d2 * rs * gv.z + bv.z;
    float o3 = d3 * rs * gv.w + bv.w;

    *reinterpret_cast<float4*>(h + base) = make_float4(o0, o1, o2, o3);

    __nv_bfloat16 h0, l0, h1, l1, h2, l2, h3, l3;
    split2(o0, h0, l0); split2(o1, h1, l1); split2(o2, h2, l2); split2(o3, h3, l3);
    __nv_bfloat162 hp0(h0, h1), hp1(h2, h3), lp0(l0, l1), lp1(l2, l3);
    uint2 hw, lw;
    hw.x = *reinterpret_cast<uint32_t*>(&hp0); hw.y = *reinterpret_cast<uint32_t*>(&hp1);
    lw.x = *reinterpret_cast<uint32_t*>(&lp0); lw.y = *reinterpret_cast<uint32_t*>(&lp1);
    *reinterpret_cast<uint2*>(&g_act0[base]) = hw;
    *reinterpret_cast<uint2*>(&g_act0[PL0 + base]) = lw;
}

// ---------------- final head ----------------
__global__ __launch_bounds__(256) void final_head_k(
    const float* __restrict__ lnfg, const float* __restrict__ lnfb,
    const float* __restrict__ Wout, const float* __restrict__ bout)
{
    __shared__ float xn[Dm];
    __shared__ float sm[32];
    const int tid = threadIdx.x;
    const int b = blockIdx.x;
    float v = g_h[(size_t)b * Tt * Dm + tid];
    float mean = bred256(v, sm) * (1.0f / Dm);
    float d = v - mean;
    float var = bred256(d * d, sm) * (1.0f / Dm);
    xn[tid] = d * rsqrtf(var + LN_EPS) * lnfg[tid] + lnfb[tid];
    __syncthreads();
    if (tid < Ed) {
        const float* w = Wout + (size_t)tid * Dm;
        float a = bout[tid];
        #pragma unroll 8
        for (int t = 0; t < Dm; t++) a += xn[t] * w[t];
        g_ze[(size_t)b * Ed + tid] = a;
    }
}

// ---------------- codebook norms + hist zero ----------------
__global__ __launch_bounds__(128) void cnorm_k(const float* __restrict__ cb) {
    __shared__ float sm[4];
    const int tid = threadIdx.x;
    float v = cb[(size_t)blockIdx.x * Ed + tid];
    v *= v;
    #pragma unroll
    for (int o = 16; o > 0; o >>= 1) v += __shfl_down_sync(0xffffffffu, v, o);
    if ((tid & 31) == 0) sm[tid >> 5] = v;
    __syncthreads();
    if (tid == 0) {
        g_cnorm[blockIdx.x] = sm[0] + sm[1] + sm[2] + sm[3];
        g_hist[blockIdx.x] = 0;
    }
}

// ---------------- VQ ----------------
__global__ __launch_bounds__(256) void vq_k(const float* __restrict__ cb) {
    __shared__ float ze[Ed];
    __shared__ float bm[256];
    __shared__ int   bi[256];
    __shared__ int   chosen;
    __shared__ float sm[32];
    const int tid = threadIdx.x;
    const int b = blockIdx.x;
    if (tid < Ed) ze[tid] = g_ze[(size_t)b * Ed + tid];
    __syncthreads();

    float best = 3.4e38f;
    int besti = 0x7fffffff;
    for (int k = tid; k < Kcb; k += 256) {
        const float* c = cb + (size_t)k * Ed;
        float dot = 0.f;
        #pragma unroll 4
        for (int e = 0; e < Ed; e++) dot += ze[e] * c[e];
        float dd = g_cnorm[k] - 2.0f * dot;
        if (dd < best || (dd == best && k < besti)) { best = dd; besti = k; }
    }
    bm[tid] = best; bi[tid] = besti;
    __syncthreads();
    for (int off = 128; off > 0; off >>= 1) {
        if (tid < off) {
            float ob = bm[tid + off]; int oi = bi[tid + off];
            if (ob < bm[tid] || (ob == bm[tid] && oi < bi[tid])) { bm[tid] = ob; bi[tid] = oi; }
        }
        __syncthreads();
    }
    if (tid == 0) {
        chosen = bi[0];
        g_idx[b] = bi[0];
        atomicAdd(&g_hist[bi[0]], 1);
    }
    __syncthreads();

    const int kk = chosen;
    float part = 0.f;
    if (tid < Ed) {
        float diff = cb[(size_t)kk * Ed + tid] - ze[tid];
        part = diff * diff;
    }
    float tot = bred256(part, sm);
    if (tid == 0) g_losspart[b] = tot;
}

// ---------------- decoder ----------------
__global__ __launch_bounds__(256) void decoder_k(
    const float* __restrict__ cb,
    const float* __restrict__ Wd1, const float* __restrict__ bd1,
    const float* __restrict__ lndg, const float* __restrict__ lndb,
    const float* __restrict__ Wd2, const float* __restrict__ bd2,
    const float* __restrict__ Wd3, const float* __restrict__ bd3,
    float* __restrict__ outp)
{
    __shared__ float zq[Ed];
    __shared__ float d1[Dm];
    __shared__ float d2s[Ed];
    __shared__ float sm[32];
    const int tid = threadIdx.x;
    const int b = blockIdx.x;
    const int ci = g_idx[b];
    if (tid < Ed) zq[tid] = cb[(size_t)ci * Ed + tid];
    __syncthreads();

    float t1 = bd1[tid];
    {
        const float* w = Wd1 + (size_t)tid * Ed;
        #pragma unroll 4
        for (int e = 0; e < Ed; e++) t1 += zq[e] * w[e];
    }
    float mean = bred256(t1, sm) * (1.0f / Dm);
    float dd = t1 - mean;
    float var = bred256(dd * dd, sm) * (1.0f / Dm);
    float xg = dd * rsqrtf(var + LN_EPS) * lndg[tid] + lndb[tid];
    d1[tid] = gelu_exact(xg);
    __syncthreads();

    if (tid < Ed) {
        const float* w2 = Wd2 + (size_t)tid * Dm;
        float t2 = bd2[tid];
        #pragma unroll 8
        for (int t = 0; t < Dm; t++) t2 += d1[t] * w2[t];
        d2s[tid] = gelu_exact(t2);
    }
    __syncthreads();

    if (tid < 2) {
        const float* w3 = Wd3 + (size_t)tid * Ed;
        float vv = bd3[tid];
        #pragma unroll 4
        for (int e = 0; e < Ed; e++) vv += d2s[e] * w3[e];
        outp[(size_t)b * 2 + tid] = vv;
    }
    if (tid == 2) outp[(size_t)Bsz * 2 + b] = (float)ci;
}

// ---------------- scalars ----------------
__global__ __launch_bounds__(1024) void scalars_k(float* __restrict__ outp) {
    __shared__ float sm[32];
    const int tid = threadIdx.x;

    float p = (float)g_hist[tid] * (1.0f / (float)Bsz);
    float term = p * logf(p + 1e-10f);
    float v = term;
    #pragma unroll
    for (int o = 16; o > 0; o >>= 1) v += __shfl_down_sync(0xffffffffu, v, o);
    if ((tid & 31) == 0) sm[tid >> 5] = v;
    __syncthreads();
    float ent = 0.f;
    if (tid == 0) {
        for (int i = 0; i < 32; i++) ent += sm[i];
        sm[0] = ent;
    }
    __syncthreads();
    ent = sm[0];
    __syncthreads();

    float lp = g_losspart[tid] + g_losspart[tid + 1024];
    #pragma unroll
    for (int o = 16; o > 0; o >>= 1) lp += __shfl_down_sync(0xffffffffu, lp, o);
    if ((tid & 31) == 0) sm[tid >> 5] = lp;
    __syncthreads();
    if (tid == 0) {
        float tot = 0.f;
        for (int i = 0; i < 32; i++) tot += sm[i];
        outp[(size_t)Bsz * 2 + Bsz + 0] = 0.1f * tot / ((float)Bsz * (float)Ed);
        outp[(size_t)Bsz * 2 + Bsz + 1] = expf(-ent);
    }
}

// ---------------- host ----------------
template <typename T>
static T* sym_addr(const void* sym) {
    void* p = nullptr;
    cudaGetSymbolAddress(&p, sym);
    return (T*)p;
}

extern "C" void kernel_launch(void* const* d_in, const int* in_sizes, int n_in,
                              void* d_out, int out_size)
{
    (void)in_sizes; (void)n_in; (void)out_size;
    const float* x     = (const float*)d_in[0];
    const float* W_in  = (const float*)d_in[1];
    const float* b_in  = (const float*)d_in[2];
    const float* cls   = (const float*)d_in[3];
    const float* Wqkv  = (const float*)d_in[4];
    const float* bqkv  = (const float*)d_in[5];
    const float* Wo    = (const float*)d_in[6];
    const float* bo    = (const float*)d_in[7];
    const float* W1    = (const float*)d_in[8];
    const float* b1    = (const float*)d_in[9];
    const float* W2    = (const float*)d_in[10];
    const float* b2    = (const float*)d_in[11];
    const float* ln1g  = (const float*)d_in[12];
    const float* ln1b  = (const float*)d_in[13];
    const float* ln2g  = (const float*)d_in[14];
    const float* ln2b  = (const float*)d_in[15];
    const float* lnfg  = (const float*)d_in[16];
    const float* lnfb  = (const float*)d_in[17];
    const float* Wout  = (const float*)d_in[18];
    const float* bout  = (const float*)d_in[19];
    const float* cb    = (const float*)d_in[20];
    const float* Wd1   = (const float*)d_in[21];
    const float* bd1   = (const float*)d_in[22];
    const float* lndg  = (const float*)d_in[23];
    const float* lndb  = (const float*)d_in[24];
    const float* Wd2   = (const float*)d_in[25];
    const float* bd2   = (const float*)d_in[26];
    const float* Wd3   = (const float*)d_in[27];
    const float* bd3   = (const float*)d_in[28];
    float* outp = (float*)d_out;

    float* pH    = sym_addr<float>(g_h);
    float* pTmp  = sym_addr<float>(g_tmp);
    __nv_bfloat16* pAct0 = sym_addr<__nv_bfloat16>(g_act0);
    __nv_bfloat16* pAct1 = sym_addr<__nv_bfloat16>(g_act1);
    __nv_bfloat16* pXb   = sym_addr<__nv_bfloat16>(g_xb);
    __nv_bfloat16* pWin  = sym_addr<__nv_bfloat16>(g_winb);
    __nv_bfloat16* pWq = sym_addr<__nv_bfloat16>(g_wqkvb);
    __nv_bfloat16* pWo = sym_addr<__nv_bfloat16>(g_wob);
    __nv_bfloat16* pW1 = sym_addr<__nv_bfloat16>(g_w1b);
    __nv_bfloat16* pW2 = sym_addr<__nv_bfloat16>(g_w2b);

    cudaFuncSetAttribute(bfgemm_k<0>, cudaFuncAttributeMaxDynamicSharedMemorySize, SMEM_DYN);
    cudaFuncSetAttribute(bfgemm_k<1>, cudaFuncAttributeMaxDynamicSharedMemorySize, SMEM_DYN);
    cudaFuncSetAttribute(bfgemm_k<2>, cudaFuncAttributeMaxDynamicSharedMemorySize, SMEM_DYN);
    cudaFuncSetAttribute(bfgemm_k<3>, cudaFuncAttributeMaxDynamicSharedMemorySize, SMEM_DYN);

    convw_k<<<1024, 256>>>(Wqkv, Wo, W1, W2);                       // 1
    prep_k<<<2048, 256>>>(x, W_in, cls);                            // 2
    bfgemm_k<3><<<dim3(Dm / 128, MIN0 / 128), 256, SMEM_DYN>>>(
        pXb, PLX, pWin, (size_t)Dm * KIN, b_in, nullptr, MIN0, Dm, KIN); // 3

    for (int i = 0; i < NL; i++) {
        bfgemm_k<2><<<dim3(768 / 128, MTOK / 128), 256, SMEM_DYN>>>(
            pAct0, PL0, pWq + (size_t)i * 2 * WQKV_SZ, (size_t)WQKV_SZ,
            bqkv + (size_t)i * 3 * Dm, nullptr, MTOK, 3 * Dm, Dm);  // 4 on i=0
        attn_k<<<Bsz * NH, 256>>>();
        bfgemm_k<0><<<dim3(Dm / 128, MTOK / 128), 256, SMEM_DYN>>>(
            pAct0, PL0, pWo + (size_t)i * 2 * WO_SZ, (size_t)WO_SZ,
            bo + (size_t)i * Dm, pTmp, MTOK, Dm, Dm);
        add_ln_k<<<MTOK / 4, 256>>>(pH, pTmp, ln1g + (size_t)i * Dm, ln1b + (size_t)i * Dm);
        bfgemm_k<1><<<dim3(FFd / 128, MTOK / 128), 256, SMEM_DYN>>>(
            pAct0, PL0, pW1 + (size_t)i * 2 * W1_SZ, (size_t)W1_SZ,
            b1 + (size_t)i * FFd, nullptr, MTOK, FFd, Dm);
        bfgemm_k<0><<<dim3(Dm / 128, MTOK / 128), 256, SMEM_DYN>>>(
            pAct1, PL1, pW2 + (size_t)i * 2 * W2_SZ, (size_t)W2_SZ,
            b2 + (size_t)i * Dm, pTmp, MTOK, Dm, FFd);
        add_ln_k<<<MTOK / 4, 256>>>(pH, pTmp, ln2g + (size_t)i * Dm, ln2b + (size_t)i * Dm);
    }

    cnorm_k<<<Kcb, 128>>>(cb);
    final_head_k<<<Bsz, 256>>>(lnfg, lnfb, Wout, bout);
    vq_k<<<Bsz, 256>>>(cb);
    decoder_k<<<Bsz, 256>>>(cb, Wd1, bd1, lndg, lndb, Wd2, bd2, Wd3, bd3, outp);
    scalars_k<<<1, 1024>>>(outp);
}

// round 15
// speedup vs baseline: 1.5500x; 1.0071x over previous
#include <cuda_runtime.h>
#include <cuda_bf16.h>
#include <math.h>
#include <stdint.h>

// ---------------- problem constants ----------------
#define Bsz 2048
#define Ssz 64
#define Cin 142
#define KIN 160
#define Dm  256
#define NH  8
#define DHd 32
#define FFd 512
#define NL  3
#define Ed  128
#define Kcb 1024
#define Tt  65
#define MTOK (Bsz*Tt)
#define MIN0 (Bsz*Ssz)
#define LN_EPS 1e-5f

#define PL0 ((size_t)MTOK*Dm)
#define PL1 ((size_t)MTOK*FFd)
#define PLQ ((size_t)MTOK*3*Dm)
#define PLX ((size_t)MIN0*KIN)
#define WQKV_SZ (3*Dm*Dm)
#define WO_SZ   (Dm*Dm)
#define W1_SZ   (FFd*Dm)
#define W2_SZ   (Dm*FFd)
#define WLAYER  (WQKV_SZ+WO_SZ+W1_SZ+W2_SZ)

// ---------------- scratch ----------------
__device__ float g_h   [(size_t)Bsz*Tt*Dm];
__device__ float g_tmp [(size_t)Bsz*Tt*Dm];
__device__ float g_ze  [(size_t)Bsz*Ed];
__device__ int   g_idx [Bsz];
__device__ float g_cnorm[Kcb];
__device__ int   g_hist[Kcb];
__device__ float g_losspart[Bsz];

__device__ __nv_bfloat16 g_act0[2*PL0];
__device__ __nv_bfloat16 g_act1[2*PL1];
__device__ __nv_bfloat16 g_qkvb[2*PLQ];
__device__ __nv_bfloat16 g_xb  [2*PLX];
__device__ __nv_bfloat16 g_winb[2*Dm*KIN];
__device__ __nv_bfloat16 g_wqkvb[(size_t)NL*2*WQKV_SZ];
__device__ __nv_bfloat16 g_wob  [(size_t)NL*2*WO_SZ];
__device__ __nv_bfloat16 g_w1b  [(size_t)NL*2*W1_SZ];
__device__ __nv_bfloat16 g_w2b  [(size_t)NL*2*W2_SZ];

// ---------------- low-level helpers ----------------
__device__ __forceinline__ uint32_t smem_to_u32(const void* p) {
    uint32_t a;
    asm("{ .reg .u64 t; cvta.to.shared.u64 t, %1; cvt.u32.u64 %0, t; }" : "=r"(a) : "l"(p));
    return a;
}
__device__ __forceinline__ void cp_async16(uint32_t saddr, const void* gaddr) {
    asm volatile("cp.async.cg.shared.global [%0], [%1], 16;" :: "r"(saddr), "l"(gaddr));
}
__device__ __forceinline__ void ldsm4(uint32_t* r, uint32_t addr) {
    asm volatile("ldmatrix.sync.aligned.m8n8.x4.shared.b16 {%0,%1,%2,%3}, [%4];"
        : "=r"(r[0]), "=r"(r[1]), "=r"(r[2]), "=r"(r[3]) : "r"(addr));
}
__device__ __forceinline__ void mma16816(float* c, const uint32_t* a, const uint32_t* b) {
    asm volatile(
        "mma.sync.aligned.m16n8k16.row.col.f32.bf16.bf16.f32 "
        "{%0,%1,%2,%3}, {%4,%5,%6,%7}, {%8,%9}, {%0,%1,%2,%3};"
        : "+f"(c[0]), "+f"(c[1]), "+f"(c[2]), "+f"(c[3])
        : "r"(a[0]), "r"(a[1]), "r"(a[2]), "r"(a[3]), "r"(b[0]), "r"(b[1]));
}
__device__ __forceinline__ float gelu_exact(float x) {
    return 0.5f * x * (1.0f + erff(x * 0.7071067811865475f));
}
__device__ __forceinline__ void split2(float v, __nv_bfloat16& h, __nv_bfloat16& l) {
    h = __float2bfloat16(v);
    l = __float2bfloat16(v - __bfloat162float(h));
}
__device__ __forceinline__ float bred256(float v, float* sm) {
    int tid = threadIdx.x;
    #pragma unroll
    for (int o = 16; o > 0; o >>= 1) v += __shfl_down_sync(0xffffffffu, v, o);
    if ((tid & 31) == 0) sm[tid >> 5] = v;
    __syncthreads();
    if (tid == 0) {
        float t = 0.f;
        #pragma unroll
        for (int i = 0; i < 8; i++) t += sm[i];
        sm[0] = t;
    }
    __syncthreads();
    float r = sm[0];
    __syncthreads();
    return r;
}
__device__ __forceinline__ float pe_val(int s, int c) {
    int j = c >> 1;
    float freq = expf(-(float)(2 * j) * (9.210340371976184f / 256.0f));
    float ang = (float)s * freq;
    return (c & 1) ? cosf(ang) : sinf(ang);
}

// ---------------- mma.sync bf16 2-split (3-term) GEMM ----------------
#define PLANE_B 8192
#define STAGE_B 32768
#define SMEM_DYN (3*STAGE_B)   // 96 KB

__device__ __forceinline__ uint32_t sw_addr(uint32_t plane_base, int r, int colk) {
    int chunk = (colk >> 3) ^ ((r >> 1) & 3);
    return plane_base + r * 64 + (chunk << 4) + ((colk & 7) << 1);
}

__device__ __forceinline__ void issue_stage(
    uint32_t sbase, const __nv_bfloat16* __restrict__ A, size_t aps,
    const __nv_bfloat16* __restrict__ W, size_t wps,
    int row0, int col0, int K, int k0, int tid)
{
    #pragma unroll
    for (int i = 0; i < 8; i++) {
        const int plane = i >> 1;
        const int idx = ((i & 1) << 8) + tid;
        const int r = idx >> 2, c16 = idx & 3;
        const __nv_bfloat16* src = (plane < 2)
            ? A + (size_t)plane * aps + (size_t)(row0 + r) * K + (k0 + c16 * 8)
            : W + (size_t)(plane - 2) * wps + (size_t)(col0 + r) * K + (k0 + c16 * 8);
        uint32_t dst = sbase + plane * PLANE_B + r * 64 + ((c16 ^ ((r >> 1) & 3)) << 4);
        cp_async16(dst, src);
    }
}

// EPI 0: residual (reads g_h) + fp32 to C. EPI 1: gelu -> act1 planes.
// EPI 2: qkvb planes. EPI 3: input-proj (PE + remap -> g_h + act0 planes)
template <int EPI>
__global__ __launch_bounds__(256, 2)
void bfgemm_k(const __nv_bfloat16* __restrict__ A, size_t aps,
              const __nv_bfloat16* __restrict__ W, size_t wps,
              const float* __restrict__ bias, float* __restrict__ C,
              int M, int N, int K)
{
    extern __shared__ char smem[];
    const uint32_t sb = smem_to_u32(smem);
    const int tid = threadIdx.x;
    const int lane = tid & 31, wid = tid >> 5;
    const int row0 = blockIdx.y * 128;
    const int col0 = blockIdx.x * 128;
    const int wm0 = (wid & 1) * 64;
    const int wn0 = (wid >> 1) * 32;
    const int qr = lane >> 2, qc = lane & 3;

    const int lj = lane >> 3;
    const int lr8 = lane & 7;
    const int a_row_off = ((lj & 1) << 3) + lr8;
    const int a_k_off   = (lj >> 1) << 3;
    const int b_row_off = ((lj >> 1) << 3) + lr8;
    const int b_k_off   = (lj & 1) << 3;

    float acc[4][4][4];
    #pragma unroll
    for (int a = 0; a < 4; a++)
        #pragma unroll
        for (int b = 0; b < 4; b++)
            #pragma unroll
            for (int c = 0; c < 4; c++) acc[a][b][c] = 0.f;

    const int nk = K >> 5;

    issue_stage(sb, A, aps, W, wps, row0, col0, K, 0, tid);
    asm volatile("cp.async.commit_group;" ::: "memory");
    issue_stage(sb + STAGE_B, A, aps, W, wps, row0, col0, K, 32, tid);
    asm volatile("cp.async.commit_group;" ::: "memory");

    for (int s = 0; s < nk; s++) {
        if (s + 1 < nk) {
            asm volatile("cp.async.wait_group 1;" ::: "memory");
        } else {
            asm volatile("cp.async.wait_group 0;" ::: "memory");
        }
        __syncthreads();
        if (s + 2 < nk) {
            issue_stage(sb + ((s + 2) % 3) * STAGE_B, A, aps, W, wps, row0, col0, K, (s + 2) << 5, tid);
            asm volatile("cp.async.commit_group;" ::: "memory");
        }

        const uint32_t stg = sb + (s % 3) * STAGE_B;
        const uint32_t ah_b = stg;
        const uint32_t al_b = stg + PLANE_B;
        const uint32_t wh_b = stg + 2 * PLANE_B;
        const uint32_t wl_b = stg + 3 * PLANE_B;

        #pragma unroll
        for (int kk = 0; kk < 32; kk += 16) {
            uint32_t areg[4][4];
            uint32_t bh[4][2], bl[4][2];

            #pragma unroll
            for (int np = 0; np < 2; np++) {
                uint32_t t4[4];
                ldsm4(t4, sw_addr(wh_b, wn0 + np * 16 + b_row_off, kk + b_k_off));
                bh[np * 2][0] = t4[0]; bh[np * 2][1] = t4[1];
                bh[np * 2 + 1][0] = t4[2]; bh[np * 2 + 1][1] = t4[3];
            }
            #pragma unroll
            for (int mi = 0; mi < 4; mi++)
                ldsm4(areg[mi], sw_addr(ah_b, wm0 + mi * 16 + a_row_off, kk + a_k_off));
            #pragma unroll
            for (int mi = 0; mi < 4; mi++)
                #pragma unroll
                for (int ni = 0; ni < 4; ni++)
                    mma16816(acc[mi][ni], areg[mi], bh[ni]);
            #pragma unroll
            for (int np = 0; np < 2; np++) {
                uint32_t t4[4];
                ldsm4(t4, sw_addr(wl_b, wn0 + np * 16 + b_row_off, kk + b_k_off));
                bl[np * 2][0] = t4[0]; bl[np * 2][1] = t4[1];
                bl[np * 2 + 1][0] = t4[2]; bl[np * 2 + 1][1] = t4[3];
            }
            #pragma unroll
            for (int mi = 0; mi < 4; mi++)
                #pragma unroll
                for (int ni = 0; ni < 4; ni++)
                    mma16816(acc[mi][ni], areg[mi], bl[ni]);
            #pragma unroll
            for (int mi = 0; mi < 4; mi++)
                ldsm4(areg[mi], sw_addr(al_b, wm0 + mi * 16 + a_row_off, kk + a_k_off));
            #pragma unroll
            for (int mi = 0; mi < 4; mi++)
                #pragma unroll
                for (int ni = 0; ni < 4; ni++)
                    mma16816(acc[mi][ni], areg[mi], bh[ni]);
        }
        __syncthreads();
    }

    // ---- epilogue ----
    #pragma unroll
    for (int mi = 0; mi < 4; mi++) {
        #pragma unroll
        for (int ni = 0; ni < 4; ni++) {
            int col = col0 + wn0 + ni * 8 + qc * 2;
            float b0 = bias[col], b1 = bias[col + 1];
            #pragma unroll
            for (int half = 0; half < 2; half++) {
                int r = row0 + wm0 + mi * 16 + qr + half * 8;
                float v0 = acc[mi][ni][half * 2 + 0] + b0;
                float v1 = acc[mi][ni][half * 2 + 1] + b1;
                if (EPI == 3) {
                    int ss = r & 63, bb = r >> 6;
                    v0 += pe_val(ss, col);
                    v1 += pe_val(ss, col + 1);
                    size_t o = ((size_t)bb * Tt + 1 + ss) * Dm + col;
                    *reinterpret_cast<float2*>(&g_h[o]) = make_float2(v0, v1);
                    __nv_bfloat16 h0, l0, h1, l1;
                    split2(v0, h0, l0);
                    split2(v1, h1, l1);
                    *reinterpret_cast<__nv_bfloat162*>(&g_act0[o]) = __nv_bfloat162(h0, h1);
                    *reinterpret_cast<__nv_bfloat162*>(&g_act0[PL0 + o]) = __nv_bfloat162(l0, l1);
                } else {
                    size_t o = (size_t)r * N + col;
                    if (EPI == 0) {
                        float2 hv = *reinterpret_cast<const float2*>(&g_h[o]);
                        *reinterpret_cast<float2*>(C + o) = make_float2(v0 + hv.x, v1 + hv.y);
                    } else if (EPI == 1) {
                        float g0 = gelu_exact(v0), g1 = gelu_exact(v1);
                        __nv_bfloat16 h0, l0, h1, l1;
                        split2(g0, h0, l0);
                        split2(g1, h1, l1);
                        *reinterpret_cast<__nv_bfloat162*>(&g_act1[o]) = __nv_bfloat162(h0, h1);
                        *reinterpret_cast<__nv_bfloat162*>(&g_act1[PL1 + o]) = __nv_bfloat162(l0, l1);
                    } else {
                        __nv_bfloat16 h0, l0, h1, l1;
                        split2(v0, h0, l0);
                        split2(v1, h1, l1);
                        *reinterpret_cast<__nv_bfloat162*>(&g_qkvb[o]) = __nv_bfloat162(h0, h1);
                        *reinterpret_cast<__nv_bfloat162*>(&g_qkvb[PLQ + o]) = __nv_bfloat162(l0, l1);
                    }
                }
            }
        }
    }
}

// ---------------- prep_all: weight splits + x/W_in planes + cls fill ----------------
__global__ __launch_bounds__(256) void prep_all_k(
    const float* __restrict__ Wqkv, const float* __restrict__ Wo,
    const float* __restrict__ W1, const float* __restrict__ W2,
    const float* __restrict__ x, const float* __restrict__ W_in,
    const float* __restrict__ cls)
{
    const size_t totConv = (size_t)NL * WLAYER;
    const size_t totX = (size_t)MIN0 * KIN;
    const size_t totW = (size_t)Dm * KIN;
    const size_t totC = (size_t)Bsz * Dm;
    const size_t total = totConv + totX + totW + totC;
    for (size_t i = (size_t)blockIdx.x * blockDim.x + threadIdx.x; i < total;
         i += (size_t)gridDim.x * blockDim.x) {
        if (i < totConv) {
            int layer = (int)(i / WLAYER);
            int off = (int)(i % WLAYER);
            float v; __nv_bfloat16 *dh, *dl;
            if (off < WQKV_SZ) {
                v = Wqkv[(size_t)layer * WQKV_SZ + off];
                dh = g_wqkvb + ((size_t)layer * 2 + 0) * WQKV_SZ + off;
                dl = g_wqkvb + ((size_t)layer * 2 + 1) * WQKV_SZ + off;
            } else if (off < WQKV_SZ + WO_SZ) {
                int o2 = off - WQKV_SZ;
                v = Wo[(size_t)layer * WO_SZ + o2];
                dh = g_wob + ((size_t)layer * 2 + 0) * WO_SZ + o2;
                dl = g_wob + ((size_t)layer * 2 + 1) * WO_SZ + o2;
            } else if (off < WQKV_SZ + WO_SZ + W1_SZ) {
                int o2 = off - WQKV_SZ - WO_SZ;
                v = W1[(size_t)layer * W1_SZ + o2];
                dh = g_w1b + ((size_t)layer * 2 + 0) * W1_SZ + o2;
                dl = g_w1b + ((size_t)layer * 2 + 1) * W1_SZ + o2;
            } else {
                int o2 = off - WQKV_SZ - WO_SZ - W1_SZ;
                v = W2[(size_t)layer * W2_SZ + o2];
                dh = g_w2b + ((size_t)layer * 2 + 0) * W2_SZ + o2;
                dl = g_w2b + ((size_t)layer * 2 + 1) * W2_SZ + o2;
            }
            __nv_bfloat16 a, b;
            split2(v, a, b);
            *dh = a; *dl = b;
        } else if (i < totConv + totX) {
            size_t j = i - totConv;
            size_t row = j / KIN;
            int k = (int)(j % KIN);
            float v = (k < Cin) ? x[row * Cin + k] : 0.f;
            __nv_bfloat16 a, b;
            split2(v, a, b);
            g_xb[j] = a;
            g_xb[PLX + j] = b;
        } else if (i < totConv + totX + totW) {
            size_t j = i - totConv - totX;
            int row = (int)(j / KIN), k = (int)(j % KIN);
            float v = (k < Cin) ? W_in[row * Cin + k] : 0.f;
            __nv_bfloat16 a, b;
            split2(v, a, b);
            g_winb[j] = a;
            g_winb[(size_t)Dm * KIN + j] = b;
        } else {
            size_t j = i - totConv - totX - totW;
            size_t bb = j / Dm;
            int d = (int)(j % Dm);
            float v = cls[d];
            size_t idx = bb * Tt * Dm + d;
            g_h[idx] = v;
            __nv_bfloat16 hh, ll;
            split2(v, hh, ll);
            g_act0[idx] = hh;
            g_act0[PL0 + idx] = ll;
        }
    }
}

// ---------------- attention: register-blocked, bf16x2 loads ----------------
#define TP 68
__global__ __launch_bounds__(256) void attn_k()
{
    const int b  = blockIdx.x >> 3;
    const int hh = blockIdx.x & 7;
    const size_t base = (size_t)b * Tt * (3 * Dm) + hh * DHd;

    __shared__ float q [TP][33];
    __shared__ float kt[TP][33];
    __shared__ float vt[TP][33];
    __shared__ float sc[TP * TP];

    const int tid = threadIdx.x;
    const int lane = tid & 31, wid = tid >> 5;

    // vectorized load: item = (t, d2) with d2 in 0..15 (pairs)
    for (int idx = tid; idx < TP * 16; idx += 256) {
        int t = idx >> 4, d2 = idx & 15;
        int d = d2 << 1;
        if (t < Tt) {
            size_t o = base + (size_t)t * (3 * Dm) + d;
            __nv_bfloat162 qh = *reinterpret_cast<const __nv_bfloat162*>(&g_qkvb[o]);
            __nv_bfloat162 ql = *reinterpret_cast<const __nv_bfloat162*>(&g_qkvb[PLQ + o]);
            __nv_bfloat162 kh = *reinterpret_cast<const __nv_bfloat162*>(&g_qkvb[o + Dm]);
            __nv_bfloat162 kl = *reinterpret_cast<const __nv_bfloat162*>(&g_qkvb[PLQ + o + Dm]);
            __nv_bfloat162 vh = *reinterpret_cast<const __nv_bfloat162*>(&g_qkvb[o + 2 * Dm]);
            __nv_bfloat162 vl = *reinterpret_cast<const __nv_bfloat162*>(&g_qkvb[PLQ + o + 2 * Dm]);
            q [t][d]     = __bfloat162float(qh.x) + __bfloat162float(ql.x);
            q [t][d + 1] = __bfloat162float(qh.y) + __bfloat162float(ql.y);
            kt[t][d]     = __bfloat162float(kh.x) + __bfloat162float(kl.x);
            kt[t][d + 1] = __bfloat162float(kh.y) + __bfloat162float(kl.y);
            vt[t][d]     = __bfloat162float(vh.x) + __bfloat162float(vl.x);
            vt[t][d + 1] = __bfloat162float(vh.y) + __bfloat162float(vl.y);
        } else {
            q[t][d] = 0.f; q[t][d + 1] = 0.f;
            kt[t][d] = 0.f; kt[t][d + 1] = 0.f;
            vt[t][d] = 0.f; vt[t][d + 1] = 0.f;
        }
    }
    __syncthreads();

    const float scale = 0.17677669529663689f;
    for (int tile = tid; tile < 289; tile += 256) {
        int ti = tile / 17, tj = tile - ti * 17;
        int i0 = ti << 2, j0 = tj << 2;
        float a2[4][4];
        #pragma unroll
        for (int a = 0; a < 4; a++)
            #pragma unroll
            for (int bq = 0; bq < 4; bq++) a2[a][bq] = 0.f;
        #pragma unroll 8
        for (int d = 0; d < DHd; d++) {
            float qv[4], kv[4];
            #pragma unroll
            for (int a = 0; a < 4; a++) qv[a] = q[i0 + a][d];
            #pragma unroll
            for (int bq = 0; bq < 4; bq++) kv[bq] = kt[j0 + bq][d];
            #pragma unroll
            for (int a = 0; a < 4; a++)
                #pragma unroll
                for (int bq = 0; bq < 4; bq++) a2[a][bq] += qv[a] * kv[bq];
        }
        #pragma unroll
        for (int a = 0; a < 4; a++)
            #pragma unroll
            for (int bq = 0; bq < 4; bq++)
                sc[(i0 + a) * TP + j0 + bq] = a2[a][bq] * scale;
    }
    __syncthreads();

    for (int r = wid; r < Tt; r += 8) {
        float* row = sc + r * TP;
        float e0 = row[lane];
        float e1 = row[32 + lane];
        float e2 = (lane == 0) ? row[64] : -3.4e38f;
        float m = fmaxf(fmaxf(e0, e1), e2);
        #pragma unroll
        for (int o = 16; o > 0; o >>= 1) m = fmaxf(m, __shfl_xor_sync(0xffffffffu, m, o));
        e0 = expf(e0 - m);
        e1 = expf(e1 - m);
        e2 = (lane == 0) ? expf(e2 - m) : 0.f;
        float s = e0 + e1 + e2;
        #pragma unroll
        for (int o = 16; o > 0; o >>= 1) s += __shfl_xor_sync(0xffffffffu, s, o);
        float inv = 1.0f / s;
        row[lane] = e0 * inv;
        row[32 + lane] = e1 * inv;
        if (lane == 0) row[64] = e2 * inv;
    }
    __syncthreads();

    for (int item = tid; item < 17 * 32; item += 256) {
        int ig = item >> 5, d = item & 31;
        int i0 = ig << 2;
        float o0 = 0.f, o1 = 0.f, o2 = 0.f, o3 = 0.f;
        #pragma unroll 5
        for (int j = 0; j < Tt; j++) {
            float vv = vt[j][d];
            o0 += sc[(i0 + 0) * TP + j] * vv;
            o1 += sc[(i0 + 1) * TP + j] * vv;
            o2 += sc[(i0 + 2) * TP + j] * vv;
            o3 += sc[(i0 + 3) * TP + j] * vv;
        }
        float ov[4] = {o0, o1, o2, o3};
        #pragma unroll
        for (int a = 0; a < 4; a++) {
            int i = i0 + a;
            if (i < Tt) {
                size_t oidx = ((size_t)b * Tt + i) * Dm + hh * DHd + d;
                __nv_bfloat16 h2, l2;
                split2(ov[a], h2, l2);
                g_act0[oidx] = h2;
                g_act0[PL0 + oidx] = l2;
            }
        }
    }
}

// ---------------- LayerNorm (input presummed in t), writes h + planes ----------------
__global__ __launch_bounds__(256) void add_ln_k(
    float* __restrict__ h, const float* __restrict__ t,
    const float* __restrict__ g, const float* __restrict__ bb)
{
    __shared__ float sms[8];
    const int tid = threadIdx.x;
    const int grp = tid >> 6;
    const int lt  = tid & 63;
    const int wid = tid >> 5;
    const size_t row = (size_t)blockIdx.x * 4 + grp;
    const size_t base = row * Dm + lt * 4;

    float4 tv = *reinterpret_cast<const float4*>(t + base);
    float v0 = tv.x, v1 = tv.y, v2 = tv.z, v3 = tv.w;

    float s = v0 + v1 + v2 + v3;
    #pragma unroll
    for (int o = 16; o > 0; o >>= 1) s += __shfl_down_sync(0xffffffffu, s, o);
    if ((tid & 31) == 0) sms[wid] = s;
    __syncthreads();
    float mean = (sms[grp * 2] + sms[grp * 2 + 1]) * (1.0f / Dm);
    __syncthreads();

    float d0 = v0 - mean, d1 = v1 - mean, d2 = v2 - mean, d3 = v3 - mean;
    float s2 = d0 * d0 + d1 * d1 + d2 * d2 + d3 * d3;
    #pragma unroll
    for (int o = 16; o > 0; o >>= 1) s2 += __shfl_down_sync(0xffffffffu, s2, o);
    if ((tid & 31) == 0) sms[wid] = s2;
    __syncthreads();
    float var = (sms[grp * 2] + sms[grp * 2 + 1]) * (1.0f / Dm);
    float rs = rsqrtf(var + LN_EPS);

    float4 gv = *reinterpret_cast<const float4*>(g + lt * 4);
    float4 bv = *reinterpret_cast<const float4*>(bb + lt * 4);
    float o0 = d0 * rs * gv.x + bv.x;
    float o1 = d1 * rs * gv.y + bv.y;
    float o2 = d2 * rs * gv.z + bv.z;
    float o3 = d3 * rs * gv.w + bv.w;

    *reinterpret_cast<float4*>(h + base) = make_float4(o0, o1, o2, o3);

    __nv_bfloat16 h0, l0, h1, l1, h2, l2, h3, l3;
    split2(o0, h0, l0); split2(o1, h1, l1); split2(o2, h2, l2); split2(o3, h3, l3);
    __nv_bfloat162 hp0(h0, h1), hp1(h2, h3), lp0(l0, l1), lp1(l2, l3);
    uint2 hw, lw;
    hw.x = *reinterpret_cast<uint32_t*>(&hp0); hw.y = *reinterpret_cast<uint32_t*>(&hp1);
    lw.x = *reinterpret_cast<uint32_t*>(&lp0); lw.y = *reinterpret_cast<uint32_t*>(&lp1);
    *reinterpret_cast<uint2*>(&g_act0[base]) = hw;
    *reinterpret_cast<uint2*>(&g_act0[PL0 + base]) = lw;
}

// ---------------- final head ----------------
__global__ __launch_bounds__(256) void final_head_k(
    const float* __restrict__ lnfg, const float* __restrict__ lnfb,
    const float* __restrict__ Wout, const float* __restrict__ bout)
{
    __shared__ float xn[Dm];
    __shared__ float sm[32];
    const int tid = threadIdx.x;
    const int b = blockIdx.x;
    float v = g_h[(size_t)b * Tt * Dm + tid];
    float mean = bred256(v, sm) * (1.0f / Dm);
    float d = v - mean;
    float var = bred256(d * d, sm) * (1.0f / Dm);
    xn[tid] = d * rsqrtf(var + LN_EPS) * lnfg[tid] + lnfb[tid];
    __syncthreads();
    if (tid < Ed) {
        const float* w = Wout + (size_t)tid * Dm;
        float a = bout[tid];
        #pragma unroll 8
        for (int t = 0; t < Dm; t++) a += xn[t] * w[t];
        g_ze[(size_t)b * Ed + tid] = a;
    }
}

// ---------------- codebook norms + hist zero ----------------
__global__ __launch_bounds__(128) void cnorm_k(const float* __restrict__ cb) {
    __shared__ float sm[4];
    const int tid = threadIdx.x;
    float v = cb[(size_t)blockIdx.x * Ed + tid];
    v *= v;
    #pragma unroll
    for (int o = 16; o > 0; o >>= 1) v += __shfl_down_sync(0xffffffffu, v, o);
    if ((tid & 31) == 0) sm[tid >> 5] = v;
    __syncthreads();
    if (tid == 0) {
        g_cnorm[blockIdx.x] = sm[0] + sm[1] + sm[2] + sm[3];
        g_hist[blockIdx.x] = 0;
    }
}

// ---------------- VQ ----------------
__global__ __launch_bounds__(256) void vq_k(const float* __restrict__ cb) {
    __shared__ float ze[Ed];
    __shared__ float bm[256];
    __shared__ int   bi[256];
    __shared__ int   chosen;
    __shared__ float sm[32];
    const int tid = threadIdx.x;
    const int b = blockIdx.x;
    if (tid < Ed) ze[tid] = g_ze[(size_t)b * Ed + tid];
    __syncthreads();

    float best = 3.4e38f;
    int besti = 0x7fffffff;
    for (int k = tid; k < Kcb; k += 256) {
        const float* c = cb + (size_t)k * Ed;
        float dot = 0.f;
        #pragma unroll 4
        for (int e = 0; e < Ed; e++) dot += ze[e] * c[e];
        float dd = g_cnorm[k] - 2.0f * dot;
        if (dd < best || (dd == best && k < besti)) { best = dd; besti = k; }
    }
    bm[tid] = best; bi[tid] = besti;
    __syncthreads();
    for (int off = 128; off > 0; off >>= 1) {
        if (tid < off) {
            float ob = bm[tid + off]; int oi = bi[tid + off];
            if (ob < bm[tid] || (ob == bm[tid] && oi < bi[tid])) { bm[tid] = ob; bi[tid] = oi; }
        }
        __syncthreads();
    }
    if (tid == 0) {
        chosen = bi[0];
        g_idx[b] = bi[0];
        atomicAdd(&g_hist[bi[0]], 1);
    }
    __syncthreads();

    const int kk = chosen;
    float part = 0.f;
    if (tid < Ed) {
        float diff = cb[(size_t)kk * Ed + tid] - ze[tid];
        part = diff * diff;
    }
    float tot = bred256(part, sm);
    if (tid == 0) g_losspart[b] = tot;
}

// ---------------- decoder ----------------
__global__ __launch_bounds__(256) void decoder_k(
    const float* __restrict__ cb,
    const float* __restrict__ Wd1, const float* __restrict__ bd1,
    const float* __restrict__ lndg, const float* __restrict__ lndb,
    const float* __restrict__ Wd2, const float* __restrict__ bd2,
    const float* __restrict__ Wd3, const float* __restrict__ bd3,
    float* __restrict__ outp)
{
    __shared__ float zq[Ed];
    __shared__ float d1[Dm];
    __shared__ float d2s[Ed];
    __shared__ float sm[32];
    const int tid = threadIdx.x;
    const int b = blockIdx.x;
    const int ci = g_idx[b];
    if (tid < Ed) zq[tid] = cb[(size_t)ci * Ed + tid];
    __syncthreads();

    float t1 = bd1[tid];
    {
        const float* w = Wd1 + (size_t)tid * Ed;
        #pragma unroll 4
        for (int e = 0; e < Ed; e++) t1 += zq[e] * w[e];
    }
    float mean = bred256(t1, sm) * (1.0f / Dm);
    float dd = t1 - mean;
    float var = bred256(dd * dd, sm) * (1.0f / Dm);
    float xg = dd * rsqrtf(var + LN_EPS) * lndg[tid] + lndb[tid];
    d1[tid] = gelu_exact(xg);
    __syncthreads();

    if (tid < Ed) {
        const float* w2 = Wd2 + (size_t)tid * Dm;
        float t2 = bd2[tid];
        #pragma unroll 8
        for (int t = 0; t < Dm; t++) t2 += d1[t] * w2[t];
        d2s[tid] = gelu_exact(t2);
    }
    __syncthreads();

    if (tid < 2) {
        const float* w3 = Wd3 + (size_t)tid * Ed;
        float vv = bd3[tid];
        #pragma unroll 4
        for (int e = 0; e < Ed; e++) vv += d2s[e] * w3[e];
        outp[(size_t)b * 2 + tid] = vv;
    }
    if (tid == 2) outp[(size_t)Bsz * 2 + b] = (float)ci;
}

// ---------------- scalars ----------------
__global__ __launch_bounds__(1024) void scalars_k(float* __restrict__ outp) {
    __shared__ float sm[32];
    const int tid = threadIdx.x;

    float p = (float)g_hist[tid] * (1.0f / (float)Bsz);
    float term = p * logf(p + 1e-10f);
    float v = term;
    #pragma unroll
    for (int o = 16; o > 0; o >>= 1) v += __shfl_down_sync(0xffffffffu, v, o);
    if ((tid & 31) == 0) sm[tid >> 5] = v;
    __syncthreads();
    float ent = 0.f;
    if (tid == 0) {
        for (int i = 0; i < 32; i++) ent += sm[i];
        sm[0] = ent;
    }
    __syncthreads();
    ent = sm[0];
    __syncthreads();

    float lp = g_losspart[tid] + g_losspart[tid + 1024];
    #pragma unroll
    for (int o = 16; o > 0; o >>= 1) lp += __shfl_down_sync(0xffffffffu, lp, o);
    if ((tid & 31) == 0) sm[tid >> 5] = lp;
    __syncthreads();
    if (tid == 0) {
        float tot = 0.f;
        for (int i = 0; i < 32; i++) tot += sm[i];
        outp[(size_t)Bsz * 2 + Bsz + 0] = 0.1f * tot / ((float)Bsz * (float)Ed);
        outp[(size_t)Bsz * 2 + Bsz + 1] = expf(-ent);
    }
}

// ---------------- host ----------------
template <typename T>
static T* sym_addr(const void* sym) {
    void* p = nullptr;
    cudaGetSymbolAddress(&p, sym);
    return (T*)p;
}

extern "C" void kernel_launch(void* const* d_in, const int* in_sizes, int n_in,
                              void* d_out, int out_size)
{
    (void)in_sizes; (void)n_in; (void)out_size;
    const float* x     = (const float*)d_in[0];
    const float* W_in  = (const float*)d_in[1];
    const float* b_in  = (const float*)d_in[2];
    const float* cls   = (const float*)d_in[3];
    const float* Wqkv  = (const float*)d_in[4];
    const float* bqkv  = (const float*)d_in[5];
    const float* Wo    = (const float*)d_in[6];
    const float* bo    = (const float*)d_in[7];
    const float* W1    = (const float*)d_in[8];
    const float* b1    = (const float*)d_in[9];
    const float* W2    = (const float*)d_in[10];
    const float* b2    = (const float*)d_in[11];
    const float* ln1g  = (const float*)d_in[12];
    const float* ln1b  = (const float*)d_in[13];
    const float* ln2g  = (const float*)d_in[14];
    const float* ln2b  = (const float*)d_in[15];
    const float* lnfg  = (const float*)d_in[16];
    const float* lnfb  = (const float*)d_in[17];
    const float* Wout  = (const float*)d_in[18];
    const float* bout  = (const float*)d_in[19];
    const float* cb    = (const float*)d_in[20];
    const float* Wd1   = (const float*)d_in[21];
    const float* bd1   = (const float*)d_in[22];
    const float* lndg  = (const float*)d_in[23];
    const float* lndb  = (const float*)d_in[24];
    const float* Wd2   = (const float*)d_in[25];
    const float* bd2   = (const float*)d_in[26];
    const float* Wd3   = (const float*)d_in[27];
    const float* bd3   = (const float*)d_in[28];
    float* outp = (float*)d_out;

    float* pH    = sym_addr<float>(g_h);
    float* pTmp  = sym_addr<float>(g_tmp);
    __nv_bfloat16* pAct0 = sym_addr<__nv_bfloat16>(g_act0);
    __nv_bfloat16* pAct1 = sym_addr<__nv_bfloat16>(g_act1);
    __nv_bfloat16* pXb   = sym_addr<__nv_bfloat16>(g_xb);
    __nv_bfloat16* pWin  = sym_addr<__nv_bfloat16>(g_winb);
    __nv_bfloat16* pWq = sym_addr<__nv_bfloat16>(g_wqkvb);
    __nv_bfloat16* pWo = sym_addr<__nv_bfloat16>(g_wob);
    __nv_bfloat16* pW1 = sym_addr<__nv_bfloat16>(g_w1b);
    __nv_bfloat16* pW2 = sym_addr<__nv_bfloat16>(g_w2b);

    cudaFuncSetAttribute(bfgemm_k<0>, cudaFuncAttributeMaxDynamicSharedMemorySize, SMEM_DYN);
    cudaFuncSetAttribute(bfgemm_k<1>, cudaFuncAttributeMaxDynamicSharedMemorySize, SMEM_DYN);
    cudaFuncSetAttribute(bfgemm_k<2>, cudaFuncAttributeMaxDynamicSharedMemorySize, SMEM_DYN);
    cudaFuncSetAttribute(bfgemm_k<3>, cudaFuncAttributeMaxDynamicSharedMemorySize, SMEM_DYN);

    prep_all_k<<<2048, 256>>>(Wqkv, Wo, W1, W2, x, W_in, cls);      // 1
    bfgemm_k<3><<<dim3(Dm / 128, MIN0 / 128), 256, SMEM_DYN>>>(
        pXb, PLX, pWin, (size_t)Dm * KIN, b_in, nullptr, MIN0, Dm, KIN); // 2

    for (int i = 0; i < NL; i++) {
        bfgemm_k<2><<<dim3(768 / 128, MTOK / 128), 256, SMEM_DYN>>>(
            pAct0, PL0, pWq + (size_t)i * 2 * WQKV_SZ, (size_t)WQKV_SZ,
            bqkv + (size_t)i * 3 * Dm, nullptr, MTOK, 3 * Dm, Dm);  // 3 on i=0
        attn_k<<<Bsz * NH, 256>>>();                                 // 4 on i=0 (ncu slot)
        bfgemm_k<0><<<dim3(Dm / 128, MTOK / 128), 256, SMEM_DYN>>>(
            pAct0, PL0, pWo + (size_t)i * 2 * WO_SZ, (size_t)WO_SZ,
            bo + (size_t)i * Dm, pTmp, MTOK, Dm, Dm);
        add_ln_k<<<MTOK / 4, 256>>>(pH, pTmp, ln1g + (size_t)i * Dm, ln1b + (size_t)i * Dm);
        bfgemm_k<1><<<dim3(FFd / 128, MTOK / 128), 256, SMEM_DYN>>>(
            pAct0, PL0, pW1 + (size_t)i * 2 * W1_SZ, (size_t)W1_SZ,
            b1 + (size_t)i * FFd, nullptr, MTOK, FFd, Dm);
        bfgemm_k<0><<<dim3(Dm / 128, MTOK / 128), 256, SMEM_DYN>>>(
            pAct1, PL1, pW2 + (size_t)i * 2 * W2_SZ, (size_t)W2_SZ,
            b2 + (size_t)i * Dm, pTmp, MTOK, Dm, FFd);
        add_ln_k<<<MTOK / 4, 256>>>(pH, pTmp, ln2g + (size_t)i * Dm, ln2b + (size_t)i * Dm);
    }

    cnorm_k<<<Kcb, 128>>>(cb);
    final_head_k<<<Bsz, 256>>>(lnfg, lnfb, Wout, bout);
    vq_k<<<Bsz, 256>>>(cb);
    decoder_k<<<Bsz, 256>>>(cb, Wd1, bd1, lndg, lndb, Wd2, bd2, Wd3, bd3, outp);
    scalars_k<<<1, 1024>>>(outp);
}

// round 16
// speedup vs baseline: 1.6500x; 1.0645x over previous
#include <cuda_runtime.h>
#include <cuda_bf16.h>
#include <math.h>
#include <stdint.h>

// ---------------- problem constants ----------------
#define Bsz 2048
#define Ssz 64
#define Cin 142
#define KIN 160
#define Dm  256
#define NH  8
#define DHd 32
#define FFd 512
#define NL  3
#define Ed  128
#define Kcb 1024
#define Tt  65
#define MTOK (Bsz*Tt)
#define MIN0 (Bsz*Ssz)
#define LN_EPS 1e-5f

#define PL0 ((size_t)MTOK*Dm)
#define PL1 ((size_t)MTOK*FFd)
#define PLQ ((size_t)MTOK*3*Dm)
#define PLX ((size_t)MIN0*KIN)
#define WQKV_SZ (3*Dm*Dm)
#define WO_SZ   (Dm*Dm)
#define W1_SZ   (FFd*Dm)
#define W2_SZ   (Dm*FFd)
#define WLAYER  (WQKV_SZ+WO_SZ+W1_SZ+W2_SZ)

// ---------------- scratch ----------------
__device__ float g_h   [(size_t)Bsz*Tt*Dm];
__device__ float g_tmp [(size_t)Bsz*Tt*Dm];
__device__ float g_ze  [(size_t)Bsz*Ed];
__device__ int   g_idx [Bsz];
__device__ float g_cnorm[Kcb];
__device__ int   g_hist[Kcb];
__device__ float g_losspart[Bsz];

__device__ __nv_bfloat16 g_act0[2*PL0];
__device__ __nv_bfloat16 g_act1[2*PL1];
__device__ __nv_bfloat16 g_qkvb[2*PLQ];
__device__ __nv_bfloat16 g_xb  [2*PLX];
__device__ __nv_bfloat16 g_winb[2*Dm*KIN];
__device__ __nv_bfloat16 g_wqkvb[(size_t)NL*2*WQKV_SZ];
__device__ __nv_bfloat16 g_wob  [(size_t)NL*2*WO_SZ];
__device__ __nv_bfloat16 g_w1b  [(size_t)NL*2*W1_SZ];
__device__ __nv_bfloat16 g_w2b  [(size_t)NL*2*W2_SZ];

// ---------------- low-level helpers ----------------
__device__ __forceinline__ uint32_t smem_to_u32(const void* p) {
    uint32_t a;
    asm("{ .reg .u64 t; cvta.to.shared.u64 t, %1; cvt.u32.u64 %0, t; }" : "=r"(a) : "l"(p));
    return a;
}
__device__ __forceinline__ void cp_async16(uint32_t saddr, const void* gaddr) {
    asm volatile("cp.async.cg.shared.global [%0], [%1], 16;" :: "r"(saddr), "l"(gaddr));
}
__device__ __forceinline__ void ldsm4(uint32_t* r, uint32_t addr) {
    asm volatile("ldmatrix.sync.aligned.m8n8.x4.shared.b16 {%0,%1,%2,%3}, [%4];"
        : "=r"(r[0]), "=r"(r[1]), "=r"(r[2]), "=r"(r[3]) : "r"(addr));
}
__device__ __forceinline__ void mma16816(float* c, const uint32_t* a, const uint32_t* b) {
    asm volatile(
        "mma.sync.aligned.m16n8k16.row.col.f32.bf16.bf16.f32 "
        "{%0,%1,%2,%3}, {%4,%5,%6,%7}, {%8,%9}, {%0,%1,%2,%3};"
        : "+f"(c[0]), "+f"(c[1]), "+f"(c[2]), "+f"(c[3])
        : "r"(a[0]), "r"(a[1]), "r"(a[2]), "r"(a[3]), "r"(b[0]), "r"(b[1]));
}
__device__ __forceinline__ float gelu_exact(float x) {
    return 0.5f * x * (1.0f + erff(x * 0.7071067811865475f));
}
__device__ __forceinline__ void split2(float v, __nv_bfloat16& h, __nv_bfloat16& l) {
    h = __float2bfloat16(v);
    l = __float2bfloat16(v - __bfloat162float(h));
}
__device__ __forceinline__ float bred256(float v, float* sm) {
    int tid = threadIdx.x;
    #pragma unroll
    for (int o = 16; o > 0; o >>= 1) v += __shfl_down_sync(0xffffffffu, v, o);
    if ((tid & 31) == 0) sm[tid >> 5] = v;
    __syncthreads();
    if (tid == 0) {
        float t = 0.f;
        #pragma unroll
        for (int i = 0; i < 8; i++) t += sm[i];
        sm[0] = t;
    }
    __syncthreads();
    float r = sm[0];
    __syncthreads();
    return r;
}
__device__ __forceinline__ float pe_val(int s, int c) {
    int j = c >> 1;
    float freq = expf(-(float)(2 * j) * (9.210340371976184f / 256.0f));
    float ang = (float)s * freq;
    return (c & 1) ? cosf(ang) : sinf(ang);
}

// ---------------- mma.sync bf16 2-split (3-term) GEMM ----------------
#define PLANE_B 8192
#define STAGE_B 32768
#define SMEM_DYN (3*STAGE_B)   // 96 KB

__device__ __forceinline__ uint32_t sw_addr(uint32_t plane_base, int r, int colk) {
    int chunk = (colk >> 3) ^ ((r >> 1) & 3);
    return plane_base + r * 64 + (chunk << 4) + ((colk & 7) << 1);
}

__device__ __forceinline__ void issue_stage(
    uint32_t sbase, const __nv_bfloat16* __restrict__ A, size_t aps,
    const __nv_bfloat16* __restrict__ W, size_t wps,
    int row0, int col0, int K, int k0, int tid)
{
    #pragma unroll
    for (int i = 0; i < 8; i++) {
        const int plane = i >> 1;
        const int idx = ((i & 1) << 8) + tid;
        const int r = idx >> 2, c16 = idx & 3;
        const __nv_bfloat16* src = (plane < 2)
            ? A + (size_t)plane * aps + (size_t)(row0 + r) * K + (k0 + c16 * 8)
            : W + (size_t)(plane - 2) * wps + (size_t)(col0 + r) * K + (k0 + c16 * 8);
        uint32_t dst = sbase + plane * PLANE_B + r * 64 + ((c16 ^ ((r >> 1) & 3)) << 4);
        cp_async16(dst, src);
    }
}

// EPI 0: residual (reads g_h) + fp32 to C. EPI 1: gelu -> act1 planes.
// EPI 2: qkvb planes. EPI 3: input-proj (PE + remap -> g_h + act0 planes)
template <int EPI>
__global__ __launch_bounds__(256, 2)
void bfgemm_k(const __nv_bfloat16* __restrict__ A, size_t aps,
              const __nv_bfloat16* __restrict__ W, size_t wps,
              const float* __restrict__ bias, float* __restrict__ C,
              int M, int N, int K)
{
    extern __shared__ char smem[];
    const uint32_t sb = smem_to_u32(smem);
    const int tid = threadIdx.x;
    const int lane = tid & 31, wid = tid >> 5;
    const int row0 = blockIdx.y * 128;
    const int col0 = blockIdx.x * 128;
    const int wm0 = (wid & 1) * 64;
    const int wn0 = (wid >> 1) * 32;
    const int qr = lane >> 2, qc = lane & 3;

    const int lj = lane >> 3;
    const int lr8 = lane & 7;
    const int a_row_off = ((lj & 1) << 3) + lr8;
    const int a_k_off   = (lj >> 1) << 3;
    const int b_row_off = ((lj >> 1) << 3) + lr8;
    const int b_k_off   = (lj & 1) << 3;

    float acc[4][4][4];
    #pragma unroll
    for (int a = 0; a < 4; a++)
        #pragma unroll
        for (int b = 0; b < 4; b++)
            #pragma unroll
            for (int c = 0; c < 4; c++) acc[a][b][c] = 0.f;

    const int nk = K >> 5;

    issue_stage(sb, A, aps, W, wps, row0, col0, K, 0, tid);
    asm volatile("cp.async.commit_group;" ::: "memory");
    issue_stage(sb + STAGE_B, A, aps, W, wps, row0, col0, K, 32, tid);
    asm volatile("cp.async.commit_group;" ::: "memory");

    for (int s = 0; s < nk; s++) {
        if (s + 1 < nk) {
            asm volatile("cp.async.wait_group 1;" ::: "memory");
        } else {
            asm volatile("cp.async.wait_group 0;" ::: "memory");
        }
        __syncthreads();
        if (s + 2 < nk) {
            issue_stage(sb + ((s + 2) % 3) * STAGE_B, A, aps, W, wps, row0, col0, K, (s + 2) << 5, tid);
            asm volatile("cp.async.commit_group;" ::: "memory");
        }

        const uint32_t stg = sb + (s % 3) * STAGE_B;
        const uint32_t ah_b = stg;
        const uint32_t al_b = stg + PLANE_B;
        const uint32_t wh_b = stg + 2 * PLANE_B;
        const uint32_t wl_b = stg + 3 * PLANE_B;

        #pragma unroll
        for (int kk = 0; kk < 32; kk += 16) {
            uint32_t areg[4][4];
            uint32_t bh[4][2], bl[4][2];

            #pragma unroll
            for (int np = 0; np < 2; np++) {
                uint32_t t4[4];
                ldsm4(t4, sw_addr(wh_b, wn0 + np * 16 + b_row_off, kk + b_k_off));
                bh[np * 2][0] = t4[0]; bh[np * 2][1] = t4[1];
                bh[np * 2 + 1][0] = t4[2]; bh[np * 2 + 1][1] = t4[3];
            }
            #pragma unroll
            for (int mi = 0; mi < 4; mi++)
                ldsm4(areg[mi], sw_addr(ah_b, wm0 + mi * 16 + a_row_off, kk + a_k_off));
            #pragma unroll
            for (int mi = 0; mi < 4; mi++)
                #pragma unroll
                for (int ni = 0; ni < 4; ni++)
                    mma16816(acc[mi][ni], areg[mi], bh[ni]);
            #pragma unroll
            for (int np = 0; np < 2; np++) {
                uint32_t t4[4];
                ldsm4(t4, sw_addr(wl_b, wn0 + np * 16 + b_row_off, kk + b_k_off));
                bl[np * 2][0] = t4[0]; bl[np * 2][1] = t4[1];
                bl[np * 2 + 1][0] = t4[2]; bl[np * 2 + 1][1] = t4[3];
            }
            #pragma unroll
            for (int mi = 0; mi < 4; mi++)
                #pragma unroll
                for (int ni = 0; ni < 4; ni++)
                    mma16816(acc[mi][ni], areg[mi], bl[ni]);
            #pragma unroll
            for (int mi = 0; mi < 4; mi++)
                ldsm4(areg[mi], sw_addr(al_b, wm0 + mi * 16 + a_row_off, kk + a_k_off));
            #pragma unroll
            for (int mi = 0; mi < 4; mi++)
                #pragma unroll
                for (int ni = 0; ni < 4; ni++)
                    mma16816(acc[mi][ni], areg[mi], bh[ni]);
        }
        __syncthreads();
    }

    // ---- epilogue ----
    #pragma unroll
    for (int mi = 0; mi < 4; mi++) {
        #pragma unroll
        for (int ni = 0; ni < 4; ni++) {
            int col = col0 + wn0 + ni * 8 + qc * 2;
            float b0 = bias[col], b1 = bias[col + 1];
            #pragma unroll
            for (int half = 0; half < 2; half++) {
                int r = row0 + wm0 + mi * 16 + qr + half * 8;
                float v0 = acc[mi][ni][half * 2 + 0] + b0;
                float v1 = acc[mi][ni][half * 2 + 1] + b1;
                if (EPI == 3) {
                    int ss = r & 63, bb = r >> 6;
                    v0 += pe_val(ss, col);
                    v1 += pe_val(ss, col + 1);
                    size_t o = ((size_t)bb * Tt + 1 + ss) * Dm + col;
                    *reinterpret_cast<float2*>(&g_h[o]) = make_float2(v0, v1);
                    __nv_bfloat16 h0, l0, h1, l1;
                    split2(v0, h0, l0);
                    split2(v1, h1, l1);
                    *reinterpret_cast<__nv_bfloat162*>(&g_act0[o]) = __nv_bfloat162(h0, h1);
                    *reinterpret_cast<__nv_bfloat162*>(&g_act0[PL0 + o]) = __nv_bfloat162(l0, l1);
                } else {
                    size_t o = (size_t)r * N + col;
                    if (EPI == 0) {
                        float2 hv = *reinterpret_cast<const float2*>(&g_h[o]);
                        *reinterpret_cast<float2*>(C + o) = make_float2(v0 + hv.x, v1 + hv.y);
                    } else if (EPI == 1) {
                        float g0 = gelu_exact(v0), g1 = gelu_exact(v1);
                        __nv_bfloat16 h0, l0, h1, l1;
                        split2(g0, h0, l0);
                        split2(g1, h1, l1);
                        *reinterpret_cast<__nv_bfloat162*>(&g_act1[o]) = __nv_bfloat162(h0, h1);
                        *reinterpret_cast<__nv_bfloat162*>(&g_act1[PL1 + o]) = __nv_bfloat162(l0, l1);
                    } else {
                        __nv_bfloat16 h0, l0, h1, l1;
                        split2(v0, h0, l0);
                        split2(v1, h1, l1);
                        *reinterpret_cast<__nv_bfloat162*>(&g_qkvb[o]) = __nv_bfloat162(h0, h1);
                        *reinterpret_cast<__nv_bfloat162*>(&g_qkvb[PLQ + o]) = __nv_bfloat162(l0, l1);
                    }
                }
            }
        }
    }
}

// ---------------- prep_all: weight splits + x/W_in planes + cls fill ----------------
__global__ __launch_bounds__(256) void prep_all_k(
    const float* __restrict__ Wqkv, const float* __restrict__ Wo,
    const float* __restrict__ W1, const float* __restrict__ W2,
    const float* __restrict__ x, const float* __restrict__ W_in,
    const float* __restrict__ cls)
{
    const size_t totConv = (size_t)NL * WLAYER;
    const size_t totX = (size_t)MIN0 * KIN;
    const size_t totW = (size_t)Dm * KIN;
    const size_t totC = (size_t)Bsz * Dm;
    const size_t total = totConv + totX + totW + totC;
    for (size_t i = (size_t)blockIdx.x * blockDim.x + threadIdx.x; i < total;
         i += (size_t)gridDim.x * blockDim.x) {
        if (i < totConv) {
            int layer = (int)(i / WLAYER);
            int off = (int)(i % WLAYER);
            float v; __nv_bfloat16 *dh, *dl;
            if (off < WQKV_SZ) {
                v = Wqkv[(size_t)layer * WQKV_SZ + off];
                dh = g_wqkvb + ((size_t)layer * 2 + 0) * WQKV_SZ + off;
                dl = g_wqkvb + ((size_t)layer * 2 + 1) * WQKV_SZ + off;
            } else if (off < WQKV_SZ + WO_SZ) {
                int o2 = off - WQKV_SZ;
                v = Wo[(size_t)layer * WO_SZ + o2];
                dh = g_wob + ((size_t)layer * 2 + 0) * WO_SZ + o2;
                dl = g_wob + ((size_t)layer * 2 + 1) * WO_SZ + o2;
            } else if (off < WQKV_SZ + WO_SZ + W1_SZ) {
                int o2 = off - WQKV_SZ - WO_SZ;
                v = W1[(size_t)layer * W1_SZ + o2];
                dh = g_w1b + ((size_t)layer * 2 + 0) * W1_SZ + o2;
                dl = g_w1b + ((size_t)layer * 2 + 1) * W1_SZ + o2;
            } else {
                int o2 = off - WQKV_SZ - WO_SZ - W1_SZ;
                v = W2[(size_t)layer * W2_SZ + o2];
                dh = g_w2b + ((size_t)layer * 2 + 0) * W2_SZ + o2;
                dl = g_w2b + ((size_t)layer * 2 + 1) * W2_SZ + o2;
            }
            __nv_bfloat16 a, b;
            split2(v, a, b);
            *dh = a; *dl = b;
        } else if (i < totConv + totX) {
            size_t j = i - totConv;
            size_t row = j / KIN;
            int k = (int)(j % KIN);
            float v = (k < Cin) ? x[row * Cin + k] : 0.f;
            __nv_bfloat16 a, b;
            split2(v, a, b);
            g_xb[j] = a;
            g_xb[PLX + j] = b;
        } else if (i < totConv + totX + totW) {
            size_t j = i - totConv - totX;
            int row = (int)(j / KIN), k = (int)(j % KIN);
            float v = (k < Cin) ? W_in[row * Cin + k] : 0.f;
            __nv_bfloat16 a, b;
            split2(v, a, b);
            g_winb[j] = a;
            g_winb[(size_t)Dm * KIN + j] = b;
        } else {
            size_t j = i - totConv - totX - totW;
            size_t bb = j / Dm;
            int d = (int)(j % Dm);
            float v = cls[d];
            size_t idx = bb * Tt * Dm + d;
            g_h[idx] = v;
            __nv_bfloat16 hh, ll;
            split2(v, hh, ll);
            g_act0[idx] = hh;
            g_act0[PL0 + idx] = ll;
        }
    }
}

// ---------------- attention: d-major smem, float4 inner loops ----------------
#define TP 68
__global__ __launch_bounds__(256) void attn_k()
{
    const int b  = blockIdx.x >> 3;
    const int hh = blockIdx.x & 7;
    const size_t base = (size_t)b * Tt * (3 * Dm) + hh * DHd;

    __shared__ float qT[DHd][TP];   // d-major: row = head dim, col = token
    __shared__ float kT[DHd][TP];
    __shared__ float vT[DHd][TP];
    __shared__ float sc[TP * TP];   // row = query i, col = key j (contiguous)

    const int tid = threadIdx.x;
    const int lane = tid & 31, wid = tid >> 5;

    // load (transposed store): item = (t, d2), d2 = pair index
    for (int idx = tid; idx < TP * 16; idx += 256) {
        int t = idx >> 4, d2 = idx & 15;
        int d = d2 << 1;
        if (t < Tt) {
            size_t o = base + (size_t)t * (3 * Dm) + d;
            __nv_bfloat162 qh = *reinterpret_cast<const __nv_bfloat162*>(&g_qkvb[o]);
            __nv_bfloat162 ql = *reinterpret_cast<const __nv_bfloat162*>(&g_qkvb[PLQ + o]);
            __nv_bfloat162 kh = *reinterpret_cast<const __nv_bfloat162*>(&g_qkvb[o + Dm]);
            __nv_bfloat162 kl = *reinterpret_cast<const __nv_bfloat162*>(&g_qkvb[PLQ + o + Dm]);
            __nv_bfloat162 vh = *reinterpret_cast<const __nv_bfloat162*>(&g_qkvb[o + 2 * Dm]);
            __nv_bfloat162 vl = *reinterpret_cast<const __nv_bfloat162*>(&g_qkvb[PLQ + o + 2 * Dm]);
            qT[d][t]     = __bfloat162float(qh.x) + __bfloat162float(ql.x);
            qT[d + 1][t] = __bfloat162float(qh.y) + __bfloat162float(ql.y);
            kT[d][t]     = __bfloat162float(kh.x) + __bfloat162float(kl.x);
            kT[d + 1][t] = __bfloat162float(kh.y) + __bfloat162float(kl.y);
            vT[d][t]     = __bfloat162float(vh.x) + __bfloat162float(vl.x);
            vT[d + 1][t] = __bfloat162float(vh.y) + __bfloat162float(vl.y);
        } else {
            qT[d][t] = 0.f; qT[d + 1][t] = 0.f;
            kT[d][t] = 0.f; kT[d + 1][t] = 0.f;
            vT[d][t] = 0.f; vT[d + 1][t] = 0.f;
        }
    }
    __syncthreads();

    // scores: 4x4 tile per thread, float4 reads along tokens
    const float scale = 0.17677669529663689f;
    for (int tile = tid; tile < 289; tile += 256) {
        int ti = tile / 17, tj = tile - ti * 17;
        int i0 = ti << 2, j0 = tj << 2;
        float a2[4][4];
        #pragma unroll
        for (int a = 0; a < 4; a++)
            #pragma unroll
            for (int bq = 0; bq < 4; bq++) a2[a][bq] = 0.f;
        #pragma unroll 8
        for (int d = 0; d < DHd; d++) {
            float4 qv = *reinterpret_cast<const float4*>(&qT[d][i0]);
            float4 kv = *reinterpret_cast<const float4*>(&kT[d][j0]);
            float qa[4] = {qv.x, qv.y, qv.z, qv.w};
            float kb[4] = {kv.x, kv.y, kv.z, kv.w};
            #pragma unroll
            for (int a = 0; a < 4; a++)
                #pragma unroll
                for (int bq = 0; bq < 4; bq++) a2[a][bq] += qa[a] * kb[bq];
        }
        #pragma unroll
        for (int a = 0; a < 4; a++) {
            float4 o4 = make_float4(a2[a][0] * scale, a2[a][1] * scale,
                                    a2[a][2] * scale, a2[a][3] * scale);
            *reinterpret_cast<float4*>(&sc[(i0 + a) * TP + j0]) = o4;
        }
    }
    __syncthreads();

    // warp-parallel softmax over valid rows (cols 65..67 hold exact zeros: kT pad = 0)
    for (int r = wid; r < Tt; r += 8) {
        float* row = sc + r * TP;
        float e0 = row[lane];
        float e1 = row[32 + lane];
        float e2 = (lane == 0) ? row[64] : -3.4e38f;
        float m = fmaxf(fmaxf(e0, e1), e2);
        #pragma unroll
        for (int o = 16; o > 0; o >>= 1) m = fmaxf(m, __shfl_xor_sync(0xffffffffu, m, o));
        e0 = expf(e0 - m);
        e1 = expf(e1 - m);
        e2 = (lane == 0) ? expf(e2 - m) : 0.f;
        float s = e0 + e1 + e2;
        #pragma unroll
        for (int o = 16; o > 0; o >>= 1) s += __shfl_xor_sync(0xffffffffu, s, o);
        float inv = 1.0f / s;
        row[lane] = e0 * inv;
        row[32 + lane] = e1 * inv;
        if (lane == 0) row[64] = e2 * inv;
    }
    __syncthreads();

    // AV: 4 query rows x 1 dim per item; float4 over keys (vT pad rows are zero)
    for (int item = tid; item < 17 * 32; item += 256) {
        int ig = item >> 5, d = item & 31;
        int i0 = ig << 2;
        float o0 = 0.f, o1 = 0.f, o2 = 0.f, o3 = 0.f;
        #pragma unroll 4
        for (int j = 0; j < TP; j += 4) {
            float4 vv = *reinterpret_cast<const float4*>(&vT[d][j]);
            float4 s0 = *reinterpret_cast<const float4*>(&sc[(i0 + 0) * TP + j]);
            float4 s1 = *reinterpret_cast<const float4*>(&sc[(i0 + 1) * TP + j]);
            float4 s2 = *reinterpret_cast<const float4*>(&sc[(i0 + 2) * TP + j]);
            float4 s3 = *reinterpret_cast<const float4*>(&sc[(i0 + 3) * TP + j]);
            o0 += s0.x * vv.x + s0.y * vv.y + s0.z * vv.z + s0.w * vv.w;
            o1 += s1.x * vv.x + s1.y * vv.y + s1.z * vv.z + s1.w * vv.w;
            o2 += s2.x * vv.x + s2.y * vv.y + s2.z * vv.z + s2.w * vv.w;
            o3 += s3.x * vv.x + s3.y * vv.y + s3.z * vv.z + s3.w * vv.w;
        }
        float ov[4] = {o0, o1, o2, o3};
        #pragma unroll
        for (int a = 0; a < 4; a++) {
            int i = i0 + a;
            if (i < Tt) {
                size_t oidx = ((size_t)b * Tt + i) * Dm + hh * DHd + d;
                __nv_bfloat16 h2, l2;
                split2(ov[a], h2, l2);
                g_act0[oidx] = h2;
                g_act0[PL0 + oidx] = l2;
            }
        }
    }
}

// ---------------- LayerNorm (input presummed in t), writes h + planes ----------------
__global__ __launch_bounds__(256) void add_ln_k(
    float* __restrict__ h, const float* __restrict__ t,
    const float* __restrict__ g, const float* __restrict__ bb)
{
    __shared__ float sms[8];
    const int tid = threadIdx.x;
    const int grp = tid >> 6;
    const int lt  = tid & 63;
    const int wid = tid >> 5;
    const size_t row = (size_t)blockIdx.x * 4 + grp;
    const size_t base = row * Dm + lt * 4;

    float4 tv = *reinterpret_cast<const float4*>(t + base);
    float v0 = tv.x, v1 = tv.y, v2 = tv.z, v3 = tv.w;

    float s = v0 + v1 + v2 + v3;
    #pragma unroll
    for (int o = 16; o > 0; o >>= 1) s += __shfl_down_sync(0xffffffffu, s, o);
    if ((tid & 31) == 0) sms[wid] = s;
    __syncthreads();
    float mean = (sms[grp * 2] + sms[grp * 2 + 1]) * (1.0f / Dm);
    __syncthreads();

    float d0 = v0 - mean, d1 = v1 - mean, d2 = v2 - mean, d3 = v3 - mean;
    float s2 = d0 * d0 + d1 * d1 + d2 * d2 + d3 * d3;
    #pragma unroll
    for (int o = 16; o > 0; o >>= 1) s2 += __shfl_down_sync(0xffffffffu, s2, o);
    if ((tid & 31) == 0) sms[wid] = s2;
    __syncthreads();
    float var = (sms[grp * 2] + sms[grp * 2 + 1]) * (1.0f / Dm);
    float rs = rsqrtf(var + LN_EPS);

    float4 gv = *reinterpret_cast<const float4*>(g + lt * 4);
    float4 bv = *reinterpret_cast<const float4*>(bb + lt * 4);
    float o0 = d0 * rs * gv.x + bv.x;
    float o1 = d1 * rs * gv.y + bv.y;
    float o2 = d2 * rs * gv.z + bv.z;
    float o3 = d3 * rs * gv.w + bv.w;

    *reinterpret_cast<float4*>(h + base) = make_float4(o0, o1, o2, o3);

    __nv_bfloat16 h0, l0, h1, l1, h2, l2, h3, l3;
    split2(o0, h0, l0); split2(o1, h1, l1); split2(o2, h2, l2); split2(o3, h3, l3);
    __nv_bfloat162 hp0(h0, h1), hp1(h2, h3), lp0(l0, l1), lp1(l2, l3);
    uint2 hw, lw;
    hw.x = *reinterpret_cast<uint32_t*>(&hp0); hw.y = *reinterpret_cast<uint32_t*>(&hp1);
    lw.x = *reinterpret_cast<uint32_t*>(&lp0); lw.y = *reinterpret_cast<uint32_t*>(&lp1);
    *reinterpret_cast<uint2*>(&g_act0[base]) = hw;
    *reinterpret_cast<uint2*>(&g_act0[PL0 + base]) = lw;
}

// ---------------- final head ----------------
__global__ __launch_bounds__(256) void final_head_k(
    const float* __restrict__ lnfg, const float* __restrict__ lnfb,
    const float* __restrict__ Wout, const float* __restrict__ bout)
{
    __shared__ float xn[Dm];
    __shared__ float sm[32];
    const int tid = threadIdx.x;
    const int b = blockIdx.x;
    float v = g_h[(size_t)b * Tt * Dm + tid];
    float mean = bred256(v, sm) * (1.0f / Dm);
    float d = v - mean;
    float var = bred256(d * d, sm) * (1.0f / Dm);
    xn[tid] = d * rsqrtf(var + LN_EPS) * lnfg[tid] + lnfb[tid];
    __syncthreads();
    if (tid < Ed) {
        const float* w = Wout + (size_t)tid * Dm;
        float a = bout[tid];
        #pragma unroll 8
        for (int t = 0; t < Dm; t++) a += xn[t] * w[t];
        g_ze[(size_t)b * Ed + tid] = a;
    }
}

// ---------------- codebook norms + hist zero ----------------
__global__ __launch_bounds__(128) void cnorm_k(const float* __restrict__ cb) {
    __shared__ float sm[4];
    const int tid = threadIdx.x;
    float v = cb[(size_t)blockIdx.x * Ed + tid];
    v *= v;
    #pragma unroll
    for (int o = 16; o > 0; o >>= 1) v += __shfl_down_sync(0xffffffffu, v, o);
    if ((tid & 31) == 0) sm[tid >> 5] = v;
    __syncthreads();
    if (tid == 0) {
        g_cnorm[blockIdx.x] = sm[0] + sm[1] + sm[2] + sm[3];
        g_hist[blockIdx.x] = 0;
    }
}

// ---------------- VQ ----------------
__global__ __launch_bounds__(256) void vq_k(const float* __restrict__ cb) {
    __shared__ float ze[Ed];
    __shared__ float bm[256];
    __shared__ int   bi[256];
    __shared__ int   chosen;
    __shared__ float sm[32];
    const int tid = threadIdx.x;
    const int b = blockIdx.x;
    if (tid < Ed) ze[tid] = g_ze[(size_t)b * Ed + tid];
    __syncthreads();

    float best = 3.4e38f;
    int besti = 0x7fffffff;
    for (int k = tid; k < Kcb; k += 256) {
        const float* c = cb + (size_t)k * Ed;
        float dot = 0.f;
        #pragma unroll 4
        for (int e = 0; e < Ed; e++) dot += ze[e] * c[e];
        float dd = g_cnorm[k] - 2.0f * dot;
        if (dd < best || (dd == best && k < besti)) { best = dd; besti = k; }
    }
    bm[tid] = best; bi[tid] = besti;
    __syncthreads();
    for (int off = 128; off > 0; off >>= 1) {
        if (tid < off) {
            float ob = bm[tid + off]; int oi = bi[tid + off];
            if (ob < bm[tid] || (ob == bm[tid] && oi < bi[tid])) { bm[tid] = ob; bi[tid] = oi; }
        }
        __syncthreads();
    }
    if (tid == 0) {
        chosen = bi[0];
        g_idx[b] = bi[0];
        atomicAdd(&g_hist[bi[0]], 1);
    }
    __syncthreads();

    const int kk = chosen;
    float part = 0.f;
    if (tid < Ed) {
        float diff = cb[(size_t)kk * Ed + tid] - ze[tid];
        part = diff * diff;
    }
    float tot = bred256(part, sm);
    if (tid == 0) g_losspart[b] = tot;
}

// ---------------- decoder ----------------
__global__ __launch_bounds__(256) void decoder_k(
    const float* __restrict__ cb,
    const float* __restrict__ Wd1, const float* __restrict__ bd1,
    const float* __restrict__ lndg, const float* __restrict__ lndb,
    const float* __restrict__ Wd2, const float* __restrict__ bd2,
    const float* __restrict__ Wd3, const float* __restrict__ bd3,
    float* __restrict__ outp)
{
    __shared__ float zq[Ed];
    __shared__ float d1[Dm];
    __shared__ float d2s[Ed];
    __shared__ float sm[32];
    const int tid = threadIdx.x;
    const int b = blockIdx.x;
    const int ci = g_idx[b];
    if (tid < Ed) zq[tid] = cb[(size_t)ci * Ed + tid];
    __syncthreads();

    float t1 = bd1[tid];
    {
        const float* w = Wd1 + (size_t)tid * Ed;
        #pragma unroll 4
        for (int e = 0; e < Ed; e++) t1 += zq[e] * w[e];
    }
    float mean = bred256(t1, sm) * (1.0f / Dm);
    float dd = t1 - mean;
    float var = bred256(dd * dd, sm) * (1.0f / Dm);
    float xg = dd * rsqrtf(var + LN_EPS) * lndg[tid] + lndb[tid];
    d1[tid] = gelu_exact(xg);
    __syncthreads();

    if (tid < Ed) {
        const float* w2 = Wd2 + (size_t)tid * Dm;
        float t2 = bd2[tid];
        #pragma unroll 8
        for (int t = 0; t < Dm; t++) t2 += d1[t] * w2[t];
        d2s[tid] = gelu_exact(t2);
    }
    __syncthreads();

    if (tid < 2) {
        const float* w3 = Wd3 + (size_t)tid * Ed;
        float vv = bd3[tid];
        #pragma unroll 4
        for (int e = 0; e < Ed; e++) vv += d2s[e] * w3[e];
        outp[(size_t)b * 2 + tid] = vv;
    }
    if (tid == 2) outp[(size_t)Bsz * 2 + b] = (float)ci;
}

// ---------------- scalars ----------------
__global__ __launch_bounds__(1024) void scalars_k(float* __restrict__ outp) {
    __shared__ float sm[32];
    const int tid = threadIdx.x;

    float p = (float)g_hist[tid] * (1.0f / (float)Bsz);
    float term = p * logf(p + 1e-10f);
    float v = term;
    #pragma unroll
    for (int o = 16; o > 0; o >>= 1) v += __shfl_down_sync(0xffffffffu, v, o);
    if ((tid & 31) == 0) sm[tid >> 5] = v;
    __syncthreads();
    float ent = 0.f;
    if (tid == 0) {
        for (int i = 0; i < 32; i++) ent += sm[i];
        sm[0] = ent;
    }
    __syncthreads();
    ent = sm[0];
    __syncthreads();

    float lp = g_losspart[tid] + g_losspart[tid + 1024];
    #pragma unroll
    for (int o = 16; o > 0; o >>= 1) lp += __shfl_down_sync(0xffffffffu, lp, o);
    if ((tid & 31) == 0) sm[tid >> 5] = lp;
    __syncthreads();
    if (tid == 0) {
        float tot = 0.f;
        for (int i = 0; i < 32; i++) tot += sm[i];
        outp[(size_t)Bsz * 2 + Bsz + 0] = 0.1f * tot / ((float)Bsz * (float)Ed);
        outp[(size_t)Bsz * 2 + Bsz + 1] = expf(-ent);
    }
}

// ---------------- host ----------------
template <typename T>
static T* sym_addr(const void* sym) {
    void* p = nullptr;
    cudaGetSymbolAddress(&p, sym);
    return (T*)p;
}

extern "C" void kernel_launch(void* const* d_in, const int* in_sizes, int n_in,
                              void* d_out, int out_size)
{
    (void)in_sizes; (void)n_in; (void)out_size;
    const float* x     = (const float*)d_in[0];
    const float* W_in  = (const float*)d_in[1];
    const float* b_in  = (const float*)d_in[2];
    const float* cls   = (const float*)d_in[3];
    const float* Wqkv  = (const float*)d_in[4];
    const float* bqkv  = (const float*)d_in[5];
    const float* Wo    = (const float*)d_in[6];
    const float* bo    = (const float*)d_in[7];
    const float* W1    = (const float*)d_in[8];
    const float* b1    = (const float*)d_in[9];
    const float* W2    = (const float*)d_in[10];
    const float* b2    = (const float*)d_in[11];
    const float* ln1g  = (const float*)d_in[12];
    const float* ln1b  = (const float*)d_in[13];
    const float* ln2g  = (const float*)d_in[14];
    const float* ln2b  = (const float*)d_in[15];
    const float* lnfg  = (const float*)d_in[16];
    const float* lnfb  = (const float*)d_in[17];
    const float* Wout  = (const float*)d_in[18];
    const float* bout  = (const float*)d_in[19];
    const float* cb    = (const float*)d_in[20];
    const float* Wd1   = (const float*)d_in[21];
    const float* bd1   = (const float*)d_in[22];
    const float* lndg  = (const float*)d_in[23];
    const float* lndb  = (const float*)d_in[24];
    const float* Wd2   = (const float*)d_in[25];
    const float* bd2   = (const float*)d_in[26];
    const float* Wd3   = (const float*)d_in[27];
    const float* bd3   = (const float*)d_in[28];
    float* outp = (float*)d_out;

    float* pH    = sym_addr<float>(g_h);
    float* pTmp  = sym_addr<float>(g_tmp);
    __nv_bfloat16* pAct0 = sym_addr<__nv_bfloat16>(g_act0);
    __nv_bfloat16* pAct1 = sym_addr<__nv_bfloat16>(g_act1);
    __nv_bfloat16* pXb   = sym_addr<__nv_bfloat16>(g_xb);
    __nv_bfloat16* pWin  = sym_addr<__nv_bfloat16>(g_winb);
    __nv_bfloat16* pWq = sym_addr<__nv_bfloat16>(g_wqkvb);
    __nv_bfloat16* pWo = sym_addr<__nv_bfloat16>(g_wob);
    __nv_bfloat16* pW1 = sym_addr<__nv_bfloat16>(g_w1b);
    __nv_bfloat16* pW2 = sym_addr<__nv_bfloat16>(g_w2b);

    cudaFuncSetAttribute(bfgemm_k<0>, cudaFuncAttributeMaxDynamicSharedMemorySize, SMEM_DYN);
    cudaFuncSetAttribute(bfgemm_k<1>, cudaFuncAttributeMaxDynamicSharedMemorySize, SMEM_DYN);
    cudaFuncSetAttribute(bfgemm_k<2>, cudaFuncAttributeMaxDynamicSharedMemorySize, SMEM_DYN);
    cudaFuncSetAttribute(bfgemm_k<3>, cudaFuncAttributeMaxDynamicSharedMemorySize, SMEM_DYN);

    prep_all_k<<<2048, 256>>>(Wqkv, Wo, W1, W2, x, W_in, cls);      // 1
    bfgemm_k<3><<<dim3(Dm / 128, MIN0 / 128), 256, SMEM_DYN>>>(
        pXb, PLX, pWin, (size_t)Dm * KIN, b_in, nullptr, MIN0, Dm, KIN); // 2

    for (int i = 0; i < NL; i++) {
        bfgemm_k<2><<<dim3(768 / 128, MTOK / 128), 256, SMEM_DYN>>>(
            pAct0, PL0, pWq + (size_t)i * 2 * WQKV_SZ, (size_t)WQKV_SZ,
            bqkv + (size_t)i * 3 * Dm, nullptr, MTOK, 3 * Dm, Dm);  // 3 on i=0
        attn_k<<<Bsz * NH, 256>>>();                                 // 4 on i=0 (ncu slot)
        bfgemm_k<0><<<dim3(Dm / 128, MTOK / 128), 256, SMEM_DYN>>>(
            pAct0, PL0, pWo + (size_t)i * 2 * WO_SZ, (size_t)WO_SZ,
            bo + (size_t)i * Dm, pTmp, MTOK, Dm, Dm);
        add_ln_k<<<MTOK / 4, 256>>>(pH, pTmp, ln1g + (size_t)i * Dm, ln1b + (size_t)i * Dm);
        bfgemm_k<1><<<dim3(FFd / 128, MTOK / 128), 256, SMEM_DYN>>>(
            pAct0, PL0, pW1 + (size_t)i * 2 * W1_SZ, (size_t)W1_SZ,
            b1 + (size_t)i * FFd, nullptr, MTOK, FFd, Dm);
        bfgemm_k<0><<<dim3(Dm / 128, MTOK / 128), 256, SMEM_DYN>>>(
            pAct1, PL1, pW2 + (size_t)i * 2 * W2_SZ, (size_t)W2_SZ,
            b2 + (size_t)i * Dm, pTmp, MTOK, Dm, FFd);
        add_ln_k<<<MTOK / 4, 256>>>(pH, pTmp, ln2g + (size_t)i * Dm, ln2b + (size_t)i * Dm);
    }

    cnorm_k<<<Kcb, 128>>>(cb);
    final_head_k<<<Bsz, 256>>>(lnfg, lnfb, Wout, bout);
    vq_k<<<Bsz, 256>>>(cb);
    decoder_k<<<Bsz, 256>>>(cb, Wd1, bd1, lndg, lndb, Wd2, bd2, Wd3, bd3, outp);
    scalars_k<<<1, 1024>>>(outp);
}

// round 17
// speedup vs baseline: 1.7077x; 1.0350x over previous
#include <cuda_runtime.h>
#include <cuda_bf16.h>
#include <math.h>
#include <stdint.h>

// ---------------- problem constants ----------------
#define Bsz 2048
#define Ssz 64
#define Cin 142
#define KIN 160
#define Dm  256
#define NH  8
#define DHd 32
#define FFd 512
#define NL  3
#define Ed  128
#define Kcb 1024
#define Tt  65
#define MTOK (Bsz*Tt)
#define MIN0 (Bsz*Ssz)
#define LN_EPS 1e-5f

#define PL0 ((size_t)MTOK*Dm)
#define PL1 ((size_t)MTOK*FFd)
#define PLQ ((size_t)MTOK*3*Dm)
#define PLX ((size_t)MIN0*KIN)
#define WQKV_SZ (3*Dm*Dm)
#define WO_SZ   (Dm*Dm)
#define W1_SZ   (FFd*Dm)
#define W2_SZ   (Dm*FFd)
#define WLAYER  (WQKV_SZ+WO_SZ+W1_SZ+W2_SZ)

// ---------------- scratch ----------------
__device__ float g_h   [(size_t)Bsz*Tt*Dm];
__device__ float g_tmp [(size_t)Bsz*Tt*Dm];
__device__ float g_ze  [(size_t)Bsz*Ed];
__device__ int   g_idx [Bsz];
__device__ float g_cnorm[Kcb];
__device__ int   g_hist[Kcb];
__device__ float g_losspart[Bsz];

__device__ __nv_bfloat16 g_act0[2*PL0];
__device__ __nv_bfloat16 g_act1[2*PL1];
__device__ __nv_bfloat16 g_qkvb[2*PLQ];
__device__ __nv_bfloat16 g_xb  [2*PLX];
__device__ __nv_bfloat16 g_winb[2*Dm*KIN];
__device__ __nv_bfloat16 g_wqkvb[(size_t)NL*2*WQKV_SZ];
__device__ __nv_bfloat16 g_wob  [(size_t)NL*2*WO_SZ];
__device__ __nv_bfloat16 g_w1b  [(size_t)NL*2*W1_SZ];
__device__ __nv_bfloat16 g_w2b  [(size_t)NL*2*W2_SZ];

// ---------------- low-level helpers ----------------
__device__ __forceinline__ uint32_t smem_to_u32(const void* p) {
    uint32_t a;
    asm("{ .reg .u64 t; cvta.to.shared.u64 t, %1; cvt.u32.u64 %0, t; }" : "=r"(a) : "l"(p));
    return a;
}
__device__ __forceinline__ void cp_async16(uint32_t saddr, const void* gaddr) {
    asm volatile("cp.async.cg.shared.global [%0], [%1], 16;" :: "r"(saddr), "l"(gaddr));
}
__device__ __forceinline__ void ldsm4(uint32_t* r, uint32_t addr) {
    asm volatile("ldmatrix.sync.aligned.m8n8.x4.shared.b16 {%0,%1,%2,%3}, [%4];"
        : "=r"(r[0]), "=r"(r[1]), "=r"(r[2]), "=r"(r[3]) : "r"(addr));
}
__device__ __forceinline__ void mma16816(float* c, const uint32_t* a, const uint32_t* b) {
    asm volatile(
        "mma.sync.aligned.m16n8k16.row.col.f32.bf16.bf16.f32 "
        "{%0,%1,%2,%3}, {%4,%5,%6,%7}, {%8,%9}, {%0,%1,%2,%3};"
        : "+f"(c[0]), "+f"(c[1]), "+f"(c[2]), "+f"(c[3])
        : "r"(a[0]), "r"(a[1]), "r"(a[2]), "r"(a[3]), "r"(b[0]), "r"(b[1]));
}
__device__ __forceinline__ float gelu_exact(float x) {
    return 0.5f * x * (1.0f + erff(x * 0.7071067811865475f));
}
__device__ __forceinline__ void split2(float v, __nv_bfloat16& h, __nv_bfloat16& l) {
    h = __float2bfloat16(v);
    l = __float2bfloat16(v - __bfloat162float(h));
}
__device__ __forceinline__ float bred256(float v, float* sm) {
    int tid = threadIdx.x;
    #pragma unroll
    for (int o = 16; o > 0; o >>= 1) v += __shfl_down_sync(0xffffffffu, v, o);
    if ((tid & 31) == 0) sm[tid >> 5] = v;
    __syncthreads();
    if (tid == 0) {
        float t = 0.f;
        #pragma unroll
        for (int i = 0; i < 8; i++) t += sm[i];
        sm[0] = t;
    }
    __syncthreads();
    float r = sm[0];
    __syncthreads();
    return r;
}
__device__ __forceinline__ float pe_val(int s, int c) {
    int j = c >> 1;
    float freq = expf(-(float)(2 * j) * (9.210340371976184f / 256.0f));
    float ang = (float)s * freq;
    return (c & 1) ? cosf(ang) : sinf(ang);
}

// ---------------- mma.sync bf16 2-split (3-term) GEMM ----------------
#define PLANE_B 8192
#define STAGE_B 32768
#define SMEM_DYN (3*STAGE_B)   // 96 KB

__device__ __forceinline__ uint32_t sw_addr(uint32_t plane_base, int r, int colk) {
    int chunk = (colk >> 3) ^ ((r >> 1) & 3);
    return plane_base + r * 64 + (chunk << 4) + ((colk & 7) << 1);
}

__device__ __forceinline__ void issue_stage(
    uint32_t sbase, const __nv_bfloat16* __restrict__ A, size_t aps,
    const __nv_bfloat16* __restrict__ W, size_t wps,
    int row0, int col0, int K, int k0, int tid)
{
    #pragma unroll
    for (int i = 0; i < 8; i++) {
        const int plane = i >> 1;
        const int idx = ((i & 1) << 8) + tid;
        const int r = idx >> 2, c16 = idx & 3;
        const __nv_bfloat16* src = (plane < 2)
            ? A + (size_t)plane * aps + (size_t)(row0 + r) * K + (k0 + c16 * 8)
            : W + (size_t)(plane - 2) * wps + (size_t)(col0 + r) * K + (k0 + c16 * 8);
        uint32_t dst = sbase + plane * PLANE_B + r * 64 + ((c16 ^ ((r >> 1) & 3)) << 4);
        cp_async16(dst, src);
    }
}

// EPI 0: residual (reads g_h) + fp32 to C. EPI 1: gelu -> act1 planes.
// EPI 2: qkvb planes. EPI 3: input-proj (PE + remap -> g_h + act0 planes)
template <int EPI>
__global__ __launch_bounds__(256, 2)
void bfgemm_k(const __nv_bfloat16* __restrict__ A, size_t aps,
              const __nv_bfloat16* __restrict__ W, size_t wps,
              const float* __restrict__ bias, float* __restrict__ C,
              int M, int N, int K)
{
    extern __shared__ char smem[];
    const uint32_t sb = smem_to_u32(smem);
    const int tid = threadIdx.x;
    const int lane = tid & 31, wid = tid >> 5;
    const int row0 = blockIdx.y * 128;
    const int col0 = blockIdx.x * 128;
    const int wm0 = (wid & 1) * 64;
    const int wn0 = (wid >> 1) * 32;
    const int qr = lane >> 2, qc = lane & 3;

    const int lj = lane >> 3;
    const int lr8 = lane & 7;
    const int a_row_off = ((lj & 1) << 3) + lr8;
    const int a_k_off   = (lj >> 1) << 3;
    const int b_row_off = ((lj >> 1) << 3) + lr8;
    const int b_k_off   = (lj & 1) << 3;

    float acc[4][4][4];
    #pragma unroll
    for (int a = 0; a < 4; a++)
        #pragma unroll
        for (int b = 0; b < 4; b++)
            #pragma unroll
            for (int c = 0; c < 4; c++) acc[a][b][c] = 0.f;

    const int nk = K >> 5;

    issue_stage(sb, A, aps, W, wps, row0, col0, K, 0, tid);
    asm volatile("cp.async.commit_group;" ::: "memory");
    issue_stage(sb + STAGE_B, A, aps, W, wps, row0, col0, K, 32, tid);
    asm volatile("cp.async.commit_group;" ::: "memory");

    for (int s = 0; s < nk; s++) {
        if (s + 1 < nk) {
            asm volatile("cp.async.wait_group 1;" ::: "memory");
        } else {
            asm volatile("cp.async.wait_group 0;" ::: "memory");
        }
        __syncthreads();
        if (s + 2 < nk) {
            issue_stage(sb + ((s + 2) % 3) * STAGE_B, A, aps, W, wps, row0, col0, K, (s + 2) << 5, tid);
            asm volatile("cp.async.commit_group;" ::: "memory");
        }

        const uint32_t stg = sb + (s % 3) * STAGE_B;
        const uint32_t ah_b = stg;
        const uint32_t al_b = stg + PLANE_B;
        const uint32_t wh_b = stg + 2 * PLANE_B;
        const uint32_t wl_b = stg + 3 * PLANE_B;

        #pragma unroll
        for (int kk = 0; kk < 32; kk += 16) {
            uint32_t areg[4][4];
            uint32_t bh[4][2], bl[4][2];

            #pragma unroll
            for (int np = 0; np < 2; np++) {
                uint32_t t4[4];
                ldsm4(t4, sw_addr(wh_b, wn0 + np * 16 + b_row_off, kk + b_k_off));
                bh[np * 2][0] = t4[0]; bh[np * 2][1] = t4[1];
                bh[np * 2 + 1][0] = t4[2]; bh[np * 2 + 1][1] = t4[3];
            }
            #pragma unroll
            for (int mi = 0; mi < 4; mi++)
                ldsm4(areg[mi], sw_addr(ah_b, wm0 + mi * 16 + a_row_off, kk + a_k_off));
            #pragma unroll
            for (int mi = 0; mi < 4; mi++)
                #pragma unroll
                for (int ni = 0; ni < 4; ni++)
                    mma16816(acc[mi][ni], areg[mi], bh[ni]);
            #pragma unroll
            for (int np = 0; np < 2; np++) {
                uint32_t t4[4];
                ldsm4(t4, sw_addr(wl_b, wn0 + np * 16 + b_row_off, kk + b_k_off));
                bl[np * 2][0] = t4[0]; bl[np * 2][1] = t4[1];
                bl[np * 2 + 1][0] = t4[2]; bl[np * 2 + 1][1] = t4[3];
            }
            #pragma unroll
            for (int mi = 0; mi < 4; mi++)
                #pragma unroll
                for (int ni = 0; ni < 4; ni++)
                    mma16816(acc[mi][ni], areg[mi], bl[ni]);
            #pragma unroll
            for (int mi = 0; mi < 4; mi++)
                ldsm4(areg[mi], sw_addr(al_b, wm0 + mi * 16 + a_row_off, kk + a_k_off));
            #pragma unroll
            for (int mi = 0; mi < 4; mi++)
                #pragma unroll
                for (int ni = 0; ni < 4; ni++)
                    mma16816(acc[mi][ni], areg[mi], bh[ni]);
        }
        __syncthreads();
    }

    // ---- epilogue ----
    #pragma unroll
    for (int mi = 0; mi < 4; mi++) {
        #pragma unroll
        for (int ni = 0; ni < 4; ni++) {
            int col = col0 + wn0 + ni * 8 + qc * 2;
            float b0 = bias[col], b1 = bias[col + 1];
            #pragma unroll
            for (int half = 0; half < 2; half++) {
                int r = row0 + wm0 + mi * 16 + qr + half * 8;
                float v0 = acc[mi][ni][half * 2 + 0] + b0;
                float v1 = acc[mi][ni][half * 2 + 1] + b1;
                if (EPI == 3) {
                    int ss = r & 63, bb = r >> 6;
                    v0 += pe_val(ss, col);
                    v1 += pe_val(ss, col + 1);
                    size_t o = ((size_t)bb * Tt + 1 + ss) * Dm + col;
                    *reinterpret_cast<float2*>(&g_h[o]) = make_float2(v0, v1);
                    __nv_bfloat16 h0, l0, h1, l1;
                    split2(v0, h0, l0);
                    split2(v1, h1, l1);
                    *reinterpret_cast<__nv_bfloat162*>(&g_act0[o]) = __nv_bfloat162(h0, h1);
                    *reinterpret_cast<__nv_bfloat162*>(&g_act0[PL0 + o]) = __nv_bfloat162(l0, l1);
                } else {
                    size_t o = (size_t)r * N + col;
                    if (EPI == 0) {
                        float2 hv = *reinterpret_cast<const float2*>(&g_h[o]);
                        *reinterpret_cast<float2*>(C + o) = make_float2(v0 + hv.x, v1 + hv.y);
                    } else if (EPI == 1) {
                        float g0 = gelu_exact(v0), g1 = gelu_exact(v1);
                        __nv_bfloat16 h0, l0, h1, l1;
                        split2(g0, h0, l0);
                        split2(g1, h1, l1);
                        *reinterpret_cast<__nv_bfloat162*>(&g_act1[o]) = __nv_bfloat162(h0, h1);
                        *reinterpret_cast<__nv_bfloat162*>(&g_act1[PL1 + o]) = __nv_bfloat162(l0, l1);
                    } else {
                        __nv_bfloat16 h0, l0, h1, l1;
                        split2(v0, h0, l0);
                        split2(v1, h1, l1);
                        *reinterpret_cast<__nv_bfloat162*>(&g_qkvb[o]) = __nv_bfloat162(h0, h1);
                        *reinterpret_cast<__nv_bfloat162*>(&g_qkvb[PLQ + o]) = __nv_bfloat162(l0, l1);
                    }
                }
            }
        }
    }
}

// ---------------- prep_all: weight splits + x/W_in planes + cls fill ----------------
__global__ __launch_bounds__(256) void prep_all_k(
    const float* __restrict__ Wqkv, const float* __restrict__ Wo,
    const float* __restrict__ W1, const float* __restrict__ W2,
    const float* __restrict__ x, const float* __restrict__ W_in,
    const float* __restrict__ cls)
{
    const size_t totConv = (size_t)NL * WLAYER;
    const size_t totX = (size_t)MIN0 * KIN;
    const size_t totW = (size_t)Dm * KIN;
    const size_t totC = (size_t)Bsz * Dm;
    const size_t total = totConv + totX + totW + totC;
    for (size_t i = (size_t)blockIdx.x * blockDim.x + threadIdx.x; i < total;
         i += (size_t)gridDim.x * blockDim.x) {
        if (i < totConv) {
            int layer = (int)(i / WLAYER);
            int off = (int)(i % WLAYER);
            float v; __nv_bfloat16 *dh, *dl;
            if (off < WQKV_SZ) {
                v = Wqkv[(size_t)layer * WQKV_SZ + off];
                dh = g_wqkvb + ((size_t)layer * 2 + 0) * WQKV_SZ + off;
                dl = g_wqkvb + ((size_t)layer * 2 + 1) * WQKV_SZ + off;
            } else if (off < WQKV_SZ + WO_SZ) {
                int o2 = off - WQKV_SZ;
                v = Wo[(size_t)layer * WO_SZ + o2];
                dh = g_wob + ((size_t)layer * 2 + 0) * WO_SZ + o2;
                dl = g_wob + ((size_t)layer * 2 + 1) * WO_SZ + o2;
            } else if (off < WQKV_SZ + WO_SZ + W1_SZ) {
                int o2 = off - WQKV_SZ - WO_SZ;
                v = W1[(size_t)layer * W1_SZ + o2];
                dh = g_w1b + ((size_t)layer * 2 + 0) * W1_SZ + o2;
                dl = g_w1b + ((size_t)layer * 2 + 1) * W1_SZ + o2;
            } else {
                int o2 = off - WQKV_SZ - WO_SZ - W1_SZ;
                v = W2[(size_t)layer * W2_SZ + o2];
                dh = g_w2b + ((size_t)layer * 2 + 0) * W2_SZ + o2;
                dl = g_w2b + ((size_t)layer * 2 + 1) * W2_SZ + o2;
            }
            __nv_bfloat16 a, b;
            split2(v, a, b);
            *dh = a; *dl = b;
        } else if (i < totConv + totX) {
            size_t j = i - totConv;
            size_t row = j / KIN;
            int k = (int)(j % KIN);
            float v = (k < Cin) ? x[row * Cin + k] : 0.f;
            __nv_bfloat16 a, b;
            split2(v, a, b);
            g_xb[j] = a;
            g_xb[PLX + j] = b;
        } else if (i < totConv + totX + totW) {
            size_t j = i - totConv - totX;
            int row = (int)(j / KIN), k = (int)(j % KIN);
            float v = (k < Cin) ? W_in[row * Cin + k] : 0.f;
            __nv_bfloat16 a, b;
            split2(v, a, b);
            g_winb[j] = a;
            g_winb[(size_t)Dm * KIN + j] = b;
        } else {
            size_t j = i - totConv - totX - totW;
            size_t bb = j / Dm;
            int d = (int)(j % Dm);
            float v = cls[d];
            size_t idx = bb * Tt * Dm + d;
            g_h[idx] = v;
            __nv_bfloat16 hh, ll;
            split2(v, hh, ll);
            g_act0[idx] = hh;
            g_act0[PL0 + idx] = ll;
        }
    }
}

// ---------------- attention: d-major q/k, t-major v, blocked AV ----------------
#define TP 68
#define VP 36
__global__ __launch_bounds__(256) void attn_k()
{
    const int b  = blockIdx.x >> 3;
    const int hh = blockIdx.x & 7;
    const size_t base = (size_t)b * Tt * (3 * Dm) + hh * DHd;

    __shared__ float qT[DHd][TP];   // d-major
    __shared__ float kT[DHd][TP];   // d-major
    __shared__ float vR[TP][VP];    // t-major (padded stride 36, 16B-aligned rows)
    __shared__ float sc[TP * TP];

    const int tid = threadIdx.x;
    const int lane = tid & 31, wid = tid >> 5;

    // load: item = (t, d2), d2 = pair index
    for (int idx = tid; idx < TP * 16; idx += 256) {
        int t = idx >> 4, d2 = idx & 15;
        int d = d2 << 1;
        if (t < Tt) {
            size_t o = base + (size_t)t * (3 * Dm) + d;
            __nv_bfloat162 qh = *reinterpret_cast<const __nv_bfloat162*>(&g_qkvb[o]);
            __nv_bfloat162 ql = *reinterpret_cast<const __nv_bfloat162*>(&g_qkvb[PLQ + o]);
            __nv_bfloat162 kh = *reinterpret_cast<const __nv_bfloat162*>(&g_qkvb[o + Dm]);
            __nv_bfloat162 kl = *reinterpret_cast<const __nv_bfloat162*>(&g_qkvb[PLQ + o + Dm]);
            __nv_bfloat162 vh = *reinterpret_cast<const __nv_bfloat162*>(&g_qkvb[o + 2 * Dm]);
            __nv_bfloat162 vl = *reinterpret_cast<const __nv_bfloat162*>(&g_qkvb[PLQ + o + 2 * Dm]);
            qT[d][t]     = __bfloat162float(qh.x) + __bfloat162float(ql.x);
            qT[d + 1][t] = __bfloat162float(qh.y) + __bfloat162float(ql.y);
            kT[d][t]     = __bfloat162float(kh.x) + __bfloat162float(kl.x);
            kT[d + 1][t] = __bfloat162float(kh.y) + __bfloat162float(kl.y);
            vR[t][d]     = __bfloat162float(vh.x) + __bfloat162float(vl.x);
            vR[t][d + 1] = __bfloat162float(vh.y) + __bfloat162float(vl.y);
        } else {
            qT[d][t] = 0.f; qT[d + 1][t] = 0.f;
            kT[d][t] = 0.f; kT[d + 1][t] = 0.f;
            vR[t][d] = 0.f; vR[t][d + 1] = 0.f;
        }
    }
    __syncthreads();

    // scores: 4x4 tile per thread, float4 reads along tokens
    const float scale = 0.17677669529663689f;
    for (int tile = tid; tile < 289; tile += 256) {
        int ti = tile / 17, tj = tile - ti * 17;
        int i0 = ti << 2, j0 = tj << 2;
        float a2[4][4];
        #pragma unroll
        for (int a = 0; a < 4; a++)
            #pragma unroll
            for (int bq = 0; bq < 4; bq++) a2[a][bq] = 0.f;
        #pragma unroll 8
        for (int d = 0; d < DHd; d++) {
            float4 qv = *reinterpret_cast<const float4*>(&qT[d][i0]);
            float4 kv = *reinterpret_cast<const float4*>(&kT[d][j0]);
            float qa[4] = {qv.x, qv.y, qv.z, qv.w};
            float kb[4] = {kv.x, kv.y, kv.z, kv.w};
            #pragma unroll
            for (int a = 0; a < 4; a++)
                #pragma unroll
                for (int bq = 0; bq < 4; bq++) a2[a][bq] += qa[a] * kb[bq];
        }
        #pragma unroll
        for (int a = 0; a < 4; a++) {
            float4 o4 = make_float4(a2[a][0] * scale, a2[a][1] * scale,
                                    a2[a][2] * scale, a2[a][3] * scale);
            *reinterpret_cast<float4*>(&sc[(i0 + a) * TP + j0]) = o4;
        }
    }
    __syncthreads();

    // warp-parallel softmax over valid rows (cols 65..67 hold exact zeros: kT pad = 0)
    for (int r = wid; r < Tt; r += 8) {
        float* row = sc + r * TP;
        float e0 = row[lane];
        float e1 = row[32 + lane];
        float e2 = (lane == 0) ? row[64] : -3.4e38f;
        float m = fmaxf(fmaxf(e0, e1), e2);
        #pragma unroll
        for (int o = 16; o > 0; o >>= 1) m = fmaxf(m, __shfl_xor_sync(0xffffffffu, m, o));
        e0 = expf(e0 - m);
        e1 = expf(e1 - m);
        e2 = (lane == 0) ? expf(e2 - m) : 0.f;
        float s = e0 + e1 + e2;
        #pragma unroll
        for (int o = 16; o > 0; o >>= 1) s += __shfl_xor_sync(0xffffffffu, s, o);
        float inv = 1.0f / s;
        row[lane] = e0 * inv;
        row[32 + lane] = e1 * inv;
        if (lane == 0) row[64] = e2 * inv;
    }
    __syncthreads();

    // AV: 4 query rows x 4 dims per thread; 136 items, float4 reads both sides
    // (sc cols 65..67 are 0; vR rows 65..67 are 0 -> padded terms vanish)
    if (tid < 136) {
        int ig = tid >> 3, dg = tid & 7;   // ig 0..16, dg 0..7
        int i0 = ig << 2, d0 = dg << 2;
        float acc[4][4];
        #pragma unroll
        for (int a = 0; a < 4; a++)
            #pragma unroll
            for (int dd = 0; dd < 4; dd++) acc[a][dd] = 0.f;

        #pragma unroll 4
        for (int j = 0; j < TP; j += 4) {
            float4 s0 = *reinterpret_cast<const float4*>(&sc[(i0 + 0) * TP + j]);
            float4 s1 = *reinterpret_cast<const float4*>(&sc[(i0 + 1) * TP + j]);
            float4 s2 = *reinterpret_cast<const float4*>(&sc[(i0 + 2) * TP + j]);
            float4 s3 = *reinterpret_cast<const float4*>(&sc[(i0 + 3) * TP + j]);
            float4 v0 = *reinterpret_cast<const float4*>(&vR[j + 0][d0]);
            float4 v1 = *reinterpret_cast<const float4*>(&vR[j + 1][d0]);
            float4 v2 = *reinterpret_cast<const float4*>(&vR[j + 2][d0]);
            float4 v3 = *reinterpret_cast<const float4*>(&vR[j + 3][d0]);
            float sv[4][4] = {{s0.x, s0.y, s0.z, s0.w}, {s1.x, s1.y, s1.z, s1.w},
                              {s2.x, s2.y, s2.z, s2.w}, {s3.x, s3.y, s3.z, s3.w}};
            float vv[4][4] = {{v0.x, v0.y, v0.z, v0.w}, {v1.x, v1.y, v1.z, v1.w},
                              {v2.x, v2.y, v2.z, v2.w}, {v3.x, v3.y, v3.z, v3.w}};
            #pragma unroll
            for (int a = 0; a < 4; a++)
                #pragma unroll
                for (int jj = 0; jj < 4; jj++)
                    #pragma unroll
                    for (int dd = 0; dd < 4; dd++)
                        acc[a][dd] += sv[a][jj] * vv[jj][dd];
        }

        #pragma unroll
        for (int a = 0; a < 4; a++) {
            int i = i0 + a;
            if (i < Tt) {
                size_t oidx = ((size_t)b * Tt + i) * Dm + hh * DHd + d0;
                __nv_bfloat16 h0, l0, h1, l1, h2, l2, h3, l3;
                split2(acc[a][0], h0, l0);
                split2(acc[a][1], h1, l1);
                split2(acc[a][2], h2, l2);
                split2(acc[a][3], h3, l3);
                __nv_bfloat162 hp0(h0, h1), hp1(h2, h3), lp0(l0, l1), lp1(l2, l3);
                uint2 hw, lw;
                hw.x = *reinterpret_cast<uint32_t*>(&hp0);
                hw.y = *reinterpret_cast<uint32_t*>(&hp1);
                lw.x = *reinterpret_cast<uint32_t*>(&lp0);
                lw.y = *reinterpret_cast<uint32_t*>(&lp1);
                *reinterpret_cast<uint2*>(&g_act0[oidx]) = hw;
                *reinterpret_cast<uint2*>(&g_act0[PL0 + oidx]) = lw;
            }
        }
    }
}

// ---------------- LayerNorm (input presummed in t), writes h + planes ----------------
__global__ __launch_bounds__(256) void add_ln_k(
    float* __restrict__ h, const float* __restrict__ t,
    const float* __restrict__ g, const float* __restrict__ bb)
{
    __shared__ float sms[8];
    const int tid = threadIdx.x;
    const int grp = tid >> 6;
    const int lt  = tid & 63;
    const int wid = tid >> 5;
    const size_t row = (size_t)blockIdx.x * 4 + grp;
    const size_t base = row * Dm + lt * 4;

    float4 tv = *reinterpret_cast<const float4*>(t + base);
    float v0 = tv.x, v1 = tv.y, v2 = tv.z, v3 = tv.w;

    float s = v0 + v1 + v2 + v3;
    #pragma unroll
    for (int o = 16; o > 0; o >>= 1) s += __shfl_down_sync(0xffffffffu, s, o);
    if ((tid & 31) == 0) sms[wid] = s;
    __syncthreads();
    float mean = (sms[grp * 2] + sms[grp * 2 + 1]) * (1.0f / Dm);
    __syncthreads();

    float d0 = v0 - mean, d1 = v1 - mean, d2 = v2 - mean, d3 = v3 - mean;
    float s2 = d0 * d0 + d1 * d1 + d2 * d2 + d3 * d3;
    #pragma unroll
    for (int o = 16; o > 0; o >>= 1) s2 += __shfl_down_sync(0xffffffffu, s2, o);
    if ((tid & 31) == 0) sms[wid] = s2;
    __syncthreads();
    float var = (sms[grp * 2] + sms[grp * 2 + 1]) * (1.0f / Dm);
    float rs = rsqrtf(var + LN_EPS);

    float4 gv = *reinterpret_cast<const float4*>(g + lt * 4);
    float4 bv = *reinterpret_cast<const float4*>(bb + lt * 4);
    float o0 = d0 * rs * gv.x + bv.x;
    float o1 = d1 * rs * gv.y + bv.y;
    float o2 = d2 * rs * gv.z + bv.z;
    float o3 = d3 * rs * gv.w + bv.w;

    *reinterpret_cast<float4*>(h + base) = make_float4(o0, o1, o2, o3);

    __nv_bfloat16 h0, l0, h1, l1, h2, l2, h3, l3;
    split2(o0, h0, l0); split2(o1, h1, l1); split2(o2, h2, l2); split2(o3, h3, l3);
    __nv_bfloat162 hp0(h0, h1), hp1(h2, h3), lp0(l0, l1), lp1(l2, l3);
    uint2 hw, lw;
    hw.x = *reinterpret_cast<uint32_t*>(&hp0); hw.y = *reinterpret_cast<uint32_t*>(&hp1);
    lw.x = *reinterpret_cast<uint32_t*>(&lp0); lw.y = *reinterpret_cast<uint32_t*>(&lp1);
    *reinterpret_cast<uint2*>(&g_act0[base]) = hw;
    *reinterpret_cast<uint2*>(&g_act0[PL0 + base]) = lw;
}

// ---------------- final head ----------------
__global__ __launch_bounds__(256) void final_head_k(
    const float* __restrict__ lnfg, const float* __restrict__ lnfb,
    const float* __restrict__ Wout, const float* __restrict__ bout)
{
    __shared__ float xn[Dm];
    __shared__ float sm[32];
    const int tid = threadIdx.x;
    const int b = blockIdx.x;
    float v = g_h[(size_t)b * Tt * Dm + tid];
    float mean = bred256(v, sm) * (1.0f / Dm);
    float d = v - mean;
    float var = bred256(d * d, sm) * (1.0f / Dm);
    xn[tid] = d * rsqrtf(var + LN_EPS) * lnfg[tid] + lnfb[tid];
    __syncthreads();
    if (tid < Ed) {
        const float* w = Wout + (size_t)tid * Dm;
        float a = bout[tid];
        #pragma unroll 8
        for (int t = 0; t < Dm; t++) a += xn[t] * w[t];
        g_ze[(size_t)b * Ed + tid] = a;
    }
}

// ---------------- codebook norms + hist zero ----------------
__global__ __launch_bounds__(128) void cnorm_k(const float* __restrict__ cb) {
    __shared__ float sm[4];
    const int tid = threadIdx.x;
    float v = cb[(size_t)blockIdx.x * Ed + tid];
    v *= v;
    #pragma unroll
    for (int o = 16; o > 0; o >>= 1) v += __shfl_down_sync(0xffffffffu, v, o);
    if ((tid & 31) == 0) sm[tid >> 5] = v;
    __syncthreads();
    if (tid == 0) {
        g_cnorm[blockIdx.x] = sm[0] + sm[1] + sm[2] + sm[3];
        g_hist[blockIdx.x] = 0;
    }
}

// ---------------- VQ ----------------
__global__ __launch_bounds__(256) void vq_k(const float* __restrict__ cb) {
    __shared__ float ze[Ed];
    __shared__ float bm[256];
    __shared__ int   bi[256];
    __shared__ int   chosen;
    __shared__ float sm[32];
    const int tid = threadIdx.x;
    const int b = blockIdx.x;
    if (tid < Ed) ze[tid] = g_ze[(size_t)b * Ed + tid];
    __syncthreads();

    float best = 3.4e38f;
    int besti = 0x7fffffff;
    for (int k = tid; k < Kcb; k += 256) {
        const float* c = cb + (size_t)k * Ed;
        float dot = 0.f;
        #pragma unroll 4
        for (int e = 0; e < Ed; e++) dot += ze[e] * c[e];
        float dd = g_cnorm[k] - 2.0f * dot;
        if (dd < best || (dd == best && k < besti)) { best = dd; besti = k; }
    }
    bm[tid] = best; bi[tid] = besti;
    __syncthreads();
    for (int off = 128; off > 0; off >>= 1) {
        if (tid < off) {
            float ob = bm[tid + off]; int oi = bi[tid + off];
            if (ob < bm[tid] || (ob == bm[tid] && oi < bi[tid])) { bm[tid] = ob; bi[tid] = oi; }
        }
        __syncthreads();
    }
    if (tid == 0) {
        chosen = bi[0];
        g_idx[b] = bi[0];
        atomicAdd(&g_hist[bi[0]], 1);
    }
    __syncthreads();

    const int kk = chosen;
    float part = 0.f;
    if (tid < Ed) {
        float diff = cb[(size_t)kk * Ed + tid] - ze[tid];
        part = diff * diff;
    }
    float tot = bred256(part, sm);
    if (tid == 0) g_losspart[b] = tot;
}

// ---------------- decoder ----------------
__global__ __launch_bounds__(256) void decoder_k(
    const float* __restrict__ cb,
    const float* __restrict__ Wd1, const float* __restrict__ bd1,
    const float* __restrict__ lndg, const float* __restrict__ lndb,
    const float* __restrict__ Wd2, const float* __restrict__ bd2,
    const float* __restrict__ Wd3, const float* __restrict__ bd3,
    float* __restrict__ outp)
{
    __shared__ float zq[Ed];
    __shared__ float d1[Dm];
    __shared__ float d2s[Ed];
    __shared__ float sm[32];
    const int tid = threadIdx.x;
    const int b = blockIdx.x;
    const int ci = g_idx[b];
    if (tid < Ed) zq[tid] = cb[(size_t)ci * Ed + tid];
    __syncthreads();

    float t1 = bd1[tid];
    {
        const float* w = Wd1 + (size_t)tid * Ed;
        #pragma unroll 4
        for (int e = 0; e < Ed; e++) t1 += zq[e] * w[e];
    }
    float mean = bred256(t1, sm) * (1.0f / Dm);
    float dd = t1 - mean;
    float var = bred256(dd * dd, sm) * (1.0f / Dm);
    float xg = dd * rsqrtf(var + LN_EPS) * lndg[tid] + lndb[tid];
    d1[tid] = gelu_exact(xg);
    __syncthreads();

    if (tid < Ed) {
        const float* w2 = Wd2 + (size_t)tid * Dm;
        float t2 = bd2[tid];
        #pragma unroll 8
        for (int t = 0; t < Dm; t++) t2 += d1[t] * w2[t];
        d2s[tid] = gelu_exact(t2);
    }
    __syncthreads();

    if (tid < 2) {
        const float* w3 = Wd3 + (size_t)tid * Ed;
        float vv = bd3[tid];
        #pragma unroll 4
        for (int e = 0; e < Ed; e++) vv += d2s[e] * w3[e];
        outp[(size_t)b * 2 + tid] = vv;
    }
    if (tid == 2) outp[(size_t)Bsz * 2 + b] = (float)ci;
}

// ---------------- scalars ----------------
__global__ __launch_bounds__(1024) void scalars_k(float* __restrict__ outp) {
    __shared__ float sm[32];
    const int tid = threadIdx.x;

    float p = (float)g_hist[tid] * (1.0f / (float)Bsz);
    float term = p * logf(p + 1e-10f);
    float v = term;
    #pragma unroll
    for (int o = 16; o > 0; o >>= 1) v += __shfl_down_sync(0xffffffffu, v, o);
    if ((tid & 31) == 0) sm[tid >> 5] = v;
    __syncthreads();
    float ent = 0.f;
    if (tid == 0) {
        for (int i = 0; i < 32; i++) ent += sm[i];
        sm[0] = ent;
    }
    __syncthreads();
    ent = sm[0];
    __syncthreads();

    float lp = g_losspart[tid] + g_losspart[tid + 1024];
    #pragma unroll
    for (int o = 16; o > 0; o >>= 1) lp += __shfl_down_sync(0xffffffffu, lp, o);
    if ((tid & 31) == 0) sm[tid >> 5] = lp;
    __syncthreads();
    if (tid == 0) {
        float tot = 0.f;
        for (int i = 0; i < 32; i++) tot += sm[i];
        outp[(size_t)Bsz * 2 + Bsz + 0] = 0.1f * tot / ((float)Bsz * (float)Ed);
        outp[(size_t)Bsz * 2 + Bsz + 1] = expf(-ent);
    }
}

// ---------------- host ----------------
template <typename T>
static T* sym_addr(const void* sym) {
    void* p = nullptr;
    cudaGetSymbolAddress(&p, sym);
    return (T*)p;
}

extern "C" void kernel_launch(void* const* d_in, const int* in_sizes, int n_in,
                              void* d_out, int out_size)
{
    (void)in_sizes; (void)n_in; (void)out_size;
    const float* x     = (const float*)d_in[0];
    const float* W_in  = (const float*)d_in[1];
    const float* b_in  = (const float*)d_in[2];
    const float* cls   = (const float*)d_in[3];
    const float* Wqkv  = (const float*)d_in[4];
    const float* bqkv  = (const float*)d_in[5];
    const float* Wo    = (const float*)d_in[6];
    const float* bo    = (const float*)d_in[7];
    const float* W1    = (const float*)d_in[8];
    const float* b1    = (const float*)d_in[9];
    const float* W2    = (const float*)d_in[10];
    const float* b2    = (const float*)d_in[11];
    const float* ln1g  = (const float*)d_in[12];
    const float* ln1b  = (const float*)d_in[13];
    const float* ln2g  = (const float*)d_in[14];
    const float* ln2b  = (const float*)d_in[15];
    const float* lnfg  = (const float*)d_in[16];
    const float* lnfb  = (const float*)d_in[17];
    const float* Wout  = (const float*)d_in[18];
    const float* bout  = (const float*)d_in[19];
    const float* cb    = (const float*)d_in[20];
    const float* Wd1   = (const float*)d_in[21];
    const float* bd1   = (const float*)d_in[22];
    const float* lndg  = (const float*)d_in[23];
    const float* lndb  = (const float*)d_in[24];
    const float* Wd2   = (const float*)d_in[25];
    const float* bd2   = (const float*)d_in[26];
    const float* Wd3   = (const float*)d_in[27];
    const float* bd3   = (const float*)d_in[28];
    float* outp = (float*)d_out;

    float* pH    = sym_addr<float>(g_h);
    float* pTmp  = sym_addr<float>(g_tmp);
    __nv_bfloat16* pAct0 = sym_addr<__nv_bfloat16>(g_act0);
    __nv_bfloat16* pAct1 = sym_addr<__nv_bfloat16>(g_act1);
    __nv_bfloat16* pXb   = sym_addr<__nv_bfloat16>(g_xb);
    __nv_bfloat16* pWin  = sym_addr<__nv_bfloat16>(g_winb);
    __nv_bfloat16* pWq = sym_addr<__nv_bfloat16>(g_wqkvb);
    __nv_bfloat16* pWo = sym_addr<__nv_bfloat16>(g_wob);
    __nv_bfloat16* pW1 = sym_addr<__nv_bfloat16>(g_w1b);
    __nv_bfloat16* pW2 = sym_addr<__nv_bfloat16>(g_w2b);

    cudaFuncSetAttribute(bfgemm_k<0>, cudaFuncAttributeMaxDynamicSharedMemorySize, SMEM_DYN);
    cudaFuncSetAttribute(bfgemm_k<1>, cudaFuncAttributeMaxDynamicSharedMemorySize, SMEM_DYN);
    cudaFuncSetAttribute(bfgemm_k<2>, cudaFuncAttributeMaxDynamicSharedMemorySize, SMEM_DYN);
    cudaFuncSetAttribute(bfgemm_k<3>, cudaFuncAttributeMaxDynamicSharedMemorySize, SMEM_DYN);

    prep_all_k<<<2048, 256>>>(Wqkv, Wo, W1, W2, x, W_in, cls);      // 1
    bfgemm_k<3><<<dim3(Dm / 128, MIN0 / 128), 256, SMEM_DYN>>>(
        pXb, PLX, pWin, (size_t)Dm * KIN, b_in, nullptr, MIN0, Dm, KIN); // 2

    for (int i = 0; i < NL; i++) {
        bfgemm_k<2><<<dim3(768 / 128, MTOK / 128), 256, SMEM_DYN>>>(
            pAct0, PL0, pWq + (size_t)i * 2 * WQKV_SZ, (size_t)WQKV_SZ,
            bqkv + (size_t)i * 3 * Dm, nullptr, MTOK, 3 * Dm, Dm);  // 3 on i=0
        attn_k<<<Bsz * NH, 256>>>();                                 // 4 on i=0 (ncu slot)
        bfgemm_k<0><<<dim3(Dm / 128, MTOK / 128), 256, SMEM_DYN>>>(
            pAct0, PL0, pWo + (size_t)i * 2 * WO_SZ, (size_t)WO_SZ,
            bo + (size_t)i * Dm, pTmp, MTOK, Dm, Dm);
        add_ln_k<<<MTOK / 4, 256>>>(pH, pTmp, ln1g + (size_t)i * Dm, ln1b + (size_t)i * Dm);
        bfgemm_k<1><<<dim3(FFd / 128, MTOK / 128), 256, SMEM_DYN>>>(
            pAct0, PL0, pW1 + (size_t)i * 2 * W1_SZ, (size_t)W1_SZ,
            b1 + (size_t)i * FFd, nullptr, MTOK, FFd, Dm);
        bfgemm_k<0><<<dim3(Dm / 128, MTOK / 128), 256, SMEM_DYN>>>(
            pAct1, PL1, pW2 + (size_t)i * 2 * W2_SZ, (size_t)W2_SZ,
            b2 + (size_t)i * Dm, pTmp, MTOK, Dm, FFd);
        add_ln_k<<<MTOK / 4, 256>>>(pH, pTmp, ln2g + (size_t)i * Dm, ln2b + (size_t)i * Dm);
    }

    cnorm_k<<<Kcb, 128>>>(cb);
    final_head_k<<<Bsz, 256>>>(lnfg, lnfb, Wout, bout);
    vq_k<<<Bsz, 256>>>(cb);
    decoder_k<<<Bsz, 256>>>(cb, Wd1, bd1, lndg, lndb, Wd2, bd2, Wd3, bd3, outp);
    scalars_k<<<1, 1024>>>(outp);
}